// round 1
// baseline (speedup 1.0000x reference)
#include <cuda_runtime.h>
#include <math.h>

#define HID   256
#define BATCH 16384
#define LK    4
#define MT    32      // rows per block
#define NTHR  512

// ---- output layout (floats), assuming tuple flattened in order ----
#define OFF_HNEXT 0
#define OFF_GSTR  (BATCH*HID)                    // 4194304
#define OFF_GNODE (OFF_GSTR + 9)                 // 4194313 (mod 4 == 1 -> scalar stores)
#define OFF_MARG  (OFF_GNODE + (long)BATCH*9*HID)
#define GN_STRIDE (9*HID)

// per-stage score accumulators: 6 stages x 4 experts
__device__ float g_s[24];

__global__ void zero_s_kernel() {
    if (threadIdx.x < 24) g_s[threadIdx.x] = 0.0f;
}

// smem layout (floats): As[MT*HID], Bs[MT*HID], Cs[4*MT*HID], Wss[HID], Ssc[4*MT]
#define SMEM_FLOATS (MT*HID*2 + 4*MT*HID + HID + 4*MT + 32)

__device__ __forceinline__ float sigmoidf_(float v) {
    return 1.0f / (1.0f + expf(-v));
}

// MODE: 0 = LIN  (A@L[k] + B@R[k] + b)
//       1 = OMZ  (1 - (A@R[k] + b))
//       2 = MUL  ((A@L[k]) * (B@R[k]) + b)
template<int MODE>
__global__ void __launch_bounds__(NTHR, 1)
stage_kernel(const float* __restrict__ A, long strideA,
             const float* __restrict__ Bv, long strideB,
             const float* __restrict__ L, const float* __restrict__ R,
             const float* __restrict__ bvec, const float* __restrict__ Ws,
             float* __restrict__ out0, long stride0,
             float* __restrict__ out1, long stride1,
             float* __restrict__ s_acc)
{
    extern __shared__ float sm[];
    float* As  = sm;
    float* Bs  = As + MT*HID;
    float* Cs  = Bs + MT*HID;
    float* Wss = Cs + 4*MT*HID;
    float* Ssc = Wss + HID;

    const int tid  = threadIdx.x;
    const long row0 = (long)blockIdx.x * MT;

    // load input tiles (scalar: stage inputs from G_node region are 4B-misaligned for f4)
    for (int idx = tid; idx < MT*HID; idx += NTHR) {
        int m = idx >> 8, n = idx & 255;
        As[idx] = A[(row0 + m) * strideA + n];
        if (MODE != 1) Bs[idx] = Bv[(row0 + m) * strideB + n];
    }
    if (tid < HID) Wss[tid] = Ws[tid];
    __syncthreads();

    const int cg = tid & 63;   // col group: cols [4*cg, 4*cg+3]
    const int rg = tid >> 6;   // row group: rows [4*rg, 4*rg+3]

    // k = 0..2 : real matmuls
    for (int k = 0; k < 3; k++) {
        const float4* Lk = reinterpret_cast<const float4*>(L + (long)k*HID*HID);
        const float4* Rk = reinterpret_cast<const float4*>(R + (long)k*HID*HID);

        float4 accL[4], accR[4];
        #pragma unroll
        for (int j = 0; j < 4; j++) {
            accL[j] = make_float4(0.f, 0.f, 0.f, 0.f);
            accR[j] = make_float4(0.f, 0.f, 0.f, 0.f);
        }

        for (int h = 0; h < HID; h += 4) {
            float4 a4[4], b4[4];
            #pragma unroll
            for (int j = 0; j < 4; j++) {
                a4[j] = *reinterpret_cast<const float4*>(&As[(rg*4 + j)*HID + h]);
                if (MODE != 1)
                    b4[j] = *reinterpret_cast<const float4*>(&Bs[(rg*4 + j)*HID + h]);
            }
            #pragma unroll
            for (int hh = 0; hh < 4; hh++) {
                float4 wl, wr;
                if (MODE != 1) wl = Lk[(h + hh)*64 + cg];
                wr = Rk[(h + hh)*64 + cg];
                #pragma unroll
                for (int j = 0; j < 4; j++) {
                    float av = reinterpret_cast<const float*>(&a4[j])[hh];
                    if (MODE == 0) {
                        float bv = reinterpret_cast<const float*>(&b4[j])[hh];
                        accL[j].x = fmaf(av, wl.x, accL[j].x);
                        accL[j].y = fmaf(av, wl.y, accL[j].y);
                        accL[j].z = fmaf(av, wl.z, accL[j].z);
                        accL[j].w = fmaf(av, wl.w, accL[j].w);
                        accL[j].x = fmaf(bv, wr.x, accL[j].x);
                        accL[j].y = fmaf(bv, wr.y, accL[j].y);
                        accL[j].z = fmaf(bv, wr.z, accL[j].z);
                        accL[j].w = fmaf(bv, wr.w, accL[j].w);
                    } else if (MODE == 1) {
                        accL[j].x = fmaf(av, wr.x, accL[j].x);
                        accL[j].y = fmaf(av, wr.y, accL[j].y);
                        accL[j].z = fmaf(av, wr.z, accL[j].z);
                        accL[j].w = fmaf(av, wr.w, accL[j].w);
                    } else {
                        float bv = reinterpret_cast<const float*>(&b4[j])[hh];
                        accL[j].x = fmaf(av, wl.x, accL[j].x);
                        accL[j].y = fmaf(av, wl.y, accL[j].y);
                        accL[j].z = fmaf(av, wl.z, accL[j].z);
                        accL[j].w = fmaf(av, wl.w, accL[j].w);
                        accR[j].x = fmaf(bv, wr.x, accR[j].x);
                        accR[j].y = fmaf(bv, wr.y, accR[j].y);
                        accR[j].z = fmaf(bv, wr.z, accR[j].z);
                        accR[j].w = fmaf(bv, wr.w, accR[j].w);
                    }
                }
            }
        }

        float4 bb = reinterpret_cast<const float4*>(bvec + k*HID)[cg];
        #pragma unroll
        for (int j = 0; j < 4; j++) {
            float4 c;
            if (MODE == 0) {
                c.x = accL[j].x + bb.x; c.y = accL[j].y + bb.y;
                c.z = accL[j].z + bb.z; c.w = accL[j].w + bb.w;
            } else if (MODE == 1) {
                c.x = 1.0f - (accL[j].x + bb.x); c.y = 1.0f - (accL[j].y + bb.y);
                c.z = 1.0f - (accL[j].z + bb.z); c.w = 1.0f - (accL[j].w + bb.w);
            } else {
                c.x = fmaf(accL[j].x, accR[j].x, bb.x);
                c.y = fmaf(accL[j].y, accR[j].y, bb.y);
                c.z = fmaf(accL[j].z, accR[j].z, bb.z);
                c.w = fmaf(accL[j].w, accR[j].w, bb.w);
            }
            *reinterpret_cast<float4*>(&Cs[k*MT*HID + (rg*4 + j)*HID + cg*4]) = c;
        }
    }

    // k = 3 : identity matrices -> elementwise
    {
        float4 b3 = reinterpret_cast<const float4*>(bvec + 3*HID)[cg];
        #pragma unroll
        for (int j = 0; j < 4; j++) {
            float4 a = *reinterpret_cast<const float4*>(&As[(rg*4 + j)*HID + cg*4]);
            float4 bq;
            if (MODE != 1) bq = *reinterpret_cast<const float4*>(&Bs[(rg*4 + j)*HID + cg*4]);
            float4 c;
            if (MODE == 0) {
                c.x = a.x + bq.x + b3.x; c.y = a.y + bq.y + b3.y;
                c.z = a.z + bq.z + b3.z; c.w = a.w + bq.w + b3.w;
            } else if (MODE == 1) {
                c.x = 1.0f - (a.x + b3.x); c.y = 1.0f - (a.y + b3.y);
                c.z = 1.0f - (a.z + b3.z); c.w = 1.0f - (a.w + b3.w);
            } else {
                c.x = fmaf(a.x, bq.x, b3.x); c.y = fmaf(a.y, bq.y, b3.y);
                c.z = fmaf(a.z, bq.z, b3.z); c.w = fmaf(a.w, bq.w, b3.w);
            }
            *reinterpret_cast<float4*>(&Cs[3*MT*HID + (rg*4 + j)*HID + cg*4]) = c;
        }
    }
    __syncthreads();

    // scores[k][m] = dot(Cs[k][m][:], Ws)  -- 128 warp-dot tasks across 16 warps
    {
        const int warp = tid >> 5, lane = tid & 31;
        for (int t = warp; t < 4*MT; t += 16) {
            int k = t >> 5, m = t & 31;
            const float* cr = &Cs[k*MT*HID + m*HID];
            float d = 0.f;
            #pragma unroll
            for (int n = lane; n < HID; n += 32) d = fmaf(cr[n], Wss[n], d);
            #pragma unroll
            for (int off = 16; off; off >>= 1) d += __shfl_down_sync(0xffffffffu, d, off);
            if (lane == 0) Ssc[t] = d;
        }
    }
    __syncthreads();

    // block-level score sums -> global accumulators (for idx/margin)
    if (tid < 4) {
        float ssum = 0.f;
        for (int m = 0; m < MT; m++) ssum += Ssc[tid*MT + m];
        atomicAdd(&s_acc[tid], ssum);
    }

    // per-row softmax combine + store
    #pragma unroll
    for (int j = 0; j < 4; j++) {
        int m = rg*4 + j;
        float s0 = Ssc[m], s1 = Ssc[32 + m], s2 = Ssc[64 + m], s3 = Ssc[96 + m];
        float mx = fmaxf(fmaxf(s0, s1), fmaxf(s2, s3));
        float e0 = expf(s0 - mx), e1 = expf(s1 - mx), e2 = expf(s2 - mx), e3 = expf(s3 - mx);
        float inv = 1.0f / (e0 + e1 + e2 + e3);
        float w0 = e0*inv, w1 = e1*inv, w2 = e2*inv, w3 = e3*inv;

        const float* c0 = &Cs[m*HID + cg*4];
        float4 v0 = *reinterpret_cast<const float4*>(c0);
        float4 v1 = *reinterpret_cast<const float4*>(c0 + 1*MT*HID);
        float4 v2 = *reinterpret_cast<const float4*>(c0 + 2*MT*HID);
        float4 v3 = *reinterpret_cast<const float4*>(c0 + 3*MT*HID);
        float ox = w0*v0.x + w1*v1.x + w2*v2.x + w3*v3.x;
        float oy = w0*v0.y + w1*v1.y + w2*v2.y + w3*v3.y;
        float oz = w0*v0.z + w1*v1.z + w2*v2.z + w3*v3.z;
        float ow = w0*v0.w + w1*v1.w + w2*v2.w + w3*v3.w;

        long ro = row0 + m;
        float* op = out0 + ro*stride0 + cg*4;
        op[0] = ox; op[1] = oy; op[2] = oz; op[3] = ow;
        if (out1) {
            float* op2 = out1 + ro*stride1 + cg*4;
            op2[0] = ox; op2[1] = oy; op2[2] = oz; op2[3] = ow;
        }
    }
}

// z1 = sigmoid(x@L0 + h@R0 + b0) -> slots 0 and 2 ; r = sigmoid(x@L1 + h@R1 + b1) -> slot 1
__global__ void __launch_bounds__(NTHR, 1)
z1r_kernel(const float* __restrict__ x, const float* __restrict__ h,
           const float* __restrict__ L, const float* __restrict__ R,
           const float* __restrict__ bvec, float* __restrict__ gnode)
{
    extern __shared__ float sm[];
    float* As = sm;
    float* Bs = As + MT*HID;

    const int tid = threadIdx.x;
    const long row0 = (long)blockIdx.x * MT;

    for (int idx = tid; idx < MT*HID; idx += NTHR) {
        int m = idx >> 8, n = idx & 255;
        As[idx] = x[(row0 + m)*HID + n];
        Bs[idx] = h[(row0 + m)*HID + n];
    }
    __syncthreads();

    const int cg = tid & 63;
    const int rg = tid >> 6;

    for (int k = 0; k < 2; k++) {
        const float4* Lk = reinterpret_cast<const float4*>(L + (long)k*HID*HID);
        const float4* Rk = reinterpret_cast<const float4*>(R + (long)k*HID*HID);
        float4 acc[4];
        #pragma unroll
        for (int j = 0; j < 4; j++) acc[j] = make_float4(0.f, 0.f, 0.f, 0.f);

        for (int hh0 = 0; hh0 < HID; hh0 += 4) {
            float4 a4[4], b4[4];
            #pragma unroll
            for (int j = 0; j < 4; j++) {
                a4[j] = *reinterpret_cast<const float4*>(&As[(rg*4 + j)*HID + hh0]);
                b4[j] = *reinterpret_cast<const float4*>(&Bs[(rg*4 + j)*HID + hh0]);
            }
            #pragma unroll
            for (int hh = 0; hh < 4; hh++) {
                float4 wl = Lk[(hh0 + hh)*64 + cg];
                float4 wr = Rk[(hh0 + hh)*64 + cg];
                #pragma unroll
                for (int j = 0; j < 4; j++) {
                    float av = reinterpret_cast<const float*>(&a4[j])[hh];
                    float bv = reinterpret_cast<const float*>(&b4[j])[hh];
                    acc[j].x = fmaf(av, wl.x, acc[j].x);
                    acc[j].y = fmaf(av, wl.y, acc[j].y);
                    acc[j].z = fmaf(av, wl.z, acc[j].z);
                    acc[j].w = fmaf(av, wl.w, acc[j].w);
                    acc[j].x = fmaf(bv, wr.x, acc[j].x);
                    acc[j].y = fmaf(bv, wr.y, acc[j].y);
                    acc[j].z = fmaf(bv, wr.z, acc[j].z);
                    acc[j].w = fmaf(bv, wr.w, acc[j].w);
                }
            }
        }

        float4 bb = reinterpret_cast<const float4*>(bvec + k*HID)[cg];
        #pragma unroll
        for (int j = 0; j < 4; j++) {
            float cx = sigmoidf_(acc[j].x + bb.x);
            float cy = sigmoidf_(acc[j].y + bb.y);
            float cz = sigmoidf_(acc[j].z + bb.z);
            float cw = sigmoidf_(acc[j].w + bb.w);
            long ro = row0 + rg*4 + j;
            float* op = gnode + ro*GN_STRIDE + k*HID + cg*4;   // slot k (0->z1, 1->r)
            op[0] = cx; op[1] = cy; op[2] = cz; op[3] = cw;
            if (k == 0) {                                      // z2 = z1 (slot 2)
                float* op2 = gnode + ro*GN_STRIDE + 2*HID + cg*4;
                op2[0] = cx; op2[1] = cy; op2[2] = cz; op2[3] = cw;
            }
        }
    }
}

__global__ void finalize_kernel(float* __restrict__ out) {
    if (threadIdx.x == 0 && blockIdx.x == 0) {
        float* gstr = out + OFF_GSTR;
        float* mg   = out + OFF_MARG;
        gstr[0] = 0.0f; gstr[1] = 1.0f; gstr[2] = 0.0f;
        for (int st = 0; st < 6; st++) {
            float s0 = g_s[st*4 + 0], s1 = g_s[st*4 + 1];
            float s2 = g_s[st*4 + 2], s3 = g_s[st*4 + 3];
            float s[4] = {s0, s1, s2, s3};
            int idx = 0; float best = s[0];
            #pragma unroll
            for (int i = 1; i < 4; i++) if (s[i] > best) { best = s[i]; idx = i; }
            float second = -INFINITY;
            #pragma unroll
            for (int i = 0; i < 4; i++) if (i != idx) second = fmaxf(second, s[i]);
            gstr[3 + st] = (float)idx;
            mg[st] = best - second;
        }
    }
}

extern "C" void kernel_launch(void* const* d_in, const int* in_sizes, int n_in,
                              void* d_out, int out_size)
{
    const float* x  = (const float*)d_in[0];
    const float* h  = (const float*)d_in[1];
    const float* L  = (const float*)d_in[2];
    const float* R  = (const float*)d_in[3];
    const float* b  = (const float*)d_in[4];
    const float* Ws = (const float*)d_in[5];
    float* out = (float*)d_out;
    float* gnode = out + OFF_GNODE;

    size_t smem = SMEM_FLOATS * sizeof(float);
    cudaFuncSetAttribute((const void*)z1r_kernel,
                         cudaFuncAttributeMaxDynamicSharedMemorySize, (int)smem);
    cudaFuncSetAttribute((const void*)stage_kernel<0>,
                         cudaFuncAttributeMaxDynamicSharedMemorySize, (int)smem);
    cudaFuncSetAttribute((const void*)stage_kernel<1>,
                         cudaFuncAttributeMaxDynamicSharedMemorySize, (int)smem);
    cudaFuncSetAttribute((const void*)stage_kernel<2>,
                         cudaFuncAttributeMaxDynamicSharedMemorySize, (int)smem);

    float* s_dev = nullptr;
    cudaGetSymbolAddress((void**)&s_dev, g_s);

    const int grid = BATCH / MT;   // 512

    zero_s_kernel<<<1, 32>>>();

    // z1 (slots 0,2), r (slot 1)
    z1r_kernel<<<grid, NTHR, smem>>>(x, h, L, R, b, gnode);

    // stage 1: rh = mixture(h@L + r@R + b) -> slot 3
    stage_kernel<0><<<grid, NTHR, smem>>>(h, (long)HID, gnode + 1*HID, (long)GN_STRIDE,
                                          L, R, b, Ws,
                                          gnode + 3*HID, (long)GN_STRIDE, nullptr, 0,
                                          s_dev + 0);
    // stage 2: h_tilde = mixture(x@L + rh@R + b) -> slot 4
    stage_kernel<0><<<grid, NTHR, smem>>>(x, (long)HID, gnode + 3*HID, (long)GN_STRIDE,
                                          L, R, b, Ws,
                                          gnode + 4*HID, (long)GN_STRIDE, nullptr, 0,
                                          s_dev + 4);
    // stage 3: oneMinusZ1 = mixture(1 - (z1@R + b)) -> slot 5
    stage_kernel<1><<<grid, NTHR, smem>>>(gnode + 0*HID, (long)GN_STRIDE, nullptr, 0,
                                          L, R, b, Ws,
                                          gnode + 5*HID, (long)GN_STRIDE, nullptr, 0,
                                          s_dev + 8);
    // stage 4: zh_tilde = mixture((h_tilde@L)*(oneMinusZ1@R) + b) -> slot 6
    stage_kernel<2><<<grid, NTHR, smem>>>(gnode + 4*HID, (long)GN_STRIDE,
                                          gnode + 5*HID, (long)GN_STRIDE,
                                          L, R, b, Ws,
                                          gnode + 6*HID, (long)GN_STRIDE, nullptr, 0,
                                          s_dev + 12);
    // stage 5: z2h = mixture((h@L)*(z2@R) + b) -> slot 7   (z2 == z1, slot 0)
    stage_kernel<2><<<grid, NTHR, smem>>>(h, (long)HID,
                                          gnode + 0*HID, (long)GN_STRIDE,
                                          L, R, b, Ws,
                                          gnode + 7*HID, (long)GN_STRIDE, nullptr, 0,
                                          s_dev + 16);
    // stage 6: h_next = mixture(zh_tilde@L + z2h@R + b) -> slot 8 + h_next output
    stage_kernel<0><<<grid, NTHR, smem>>>(gnode + 6*HID, (long)GN_STRIDE,
                                          gnode + 7*HID, (long)GN_STRIDE,
                                          L, R, b, Ws,
                                          gnode + 8*HID, (long)GN_STRIDE,
                                          out + OFF_HNEXT, (long)HID,
                                          s_dev + 20);

    finalize_kernel<<<1, 32>>>(out);
}

// round 2
// speedup vs baseline: 1.5967x; 1.5967x over previous
#include <cuda_runtime.h>
#include <math.h>

#define HID   256
#define BATCH 16384
#define LK    4
#define MT    32      // rows per block
#define NTHR  512

// ---- output layout (floats), assuming tuple flattened in order ----
#define OFF_HNEXT 0
#define OFF_GSTR  (BATCH*HID)                    // 4194304
#define OFF_GNODE (OFF_GSTR + 9)                 // 4194313 (mod 4 == 1 -> scalar stores)
#define OFF_MARG  (OFF_GNODE + (long)BATCH*9*HID)
#define GN_STRIDE (9*HID)

// per-stage score accumulators: 6 stages x 4 experts
__device__ float g_s[24];

__global__ void zero_s_kernel() {
    if (threadIdx.x < 24) g_s[threadIdx.x] = 0.0f;
}

// smem layout (floats): As[MT*HID], Bs[MT*HID], Cs[4*MT*HID], Wss[HID], Ssc[4*MT]
#define SMEM_FLOATS (MT*HID*2 + 4*MT*HID + HID + 4*MT + 32)

__device__ __forceinline__ float sigmoidf_(float v) {
    return 1.0f / (1.0f + expf(-v));
}

// MODE: 0 = LIN  (A@L[k] + B@R[k] + b)
//       1 = OMZ  (1 - (A@R[k] + b))
//       2 = MUL  ((A@L[k]) * (B@R[k]) + b)
template<int MODE>
__global__ void __launch_bounds__(NTHR, 1)
stage_kernel(const float* __restrict__ A, long strideA,
             const float* __restrict__ Bv, long strideB,
             const float* __restrict__ L, const float* __restrict__ R,
             const float* __restrict__ bvec, const float* __restrict__ Ws,
             float* __restrict__ out0, long stride0,
             float* __restrict__ out1, long stride1,
             float* __restrict__ s_acc)
{
    extern __shared__ float sm[];
    float* As  = sm;
    float* Bs  = As + MT*HID;
    float* Cs  = Bs + MT*HID;
    float* Wss = Cs + 4*MT*HID;
    float* Ssc = Wss + HID;

    const int tid  = threadIdx.x;
    const long row0 = (long)blockIdx.x * MT;

    // load input tiles (scalar: stage inputs from G_node region are 4B-misaligned for f4)
    for (int idx = tid; idx < MT*HID; idx += NTHR) {
        int m = idx >> 8, n = idx & 255;
        As[idx] = A[(row0 + m) * strideA + n];
        if (MODE != 1) Bs[idx] = Bv[(row0 + m) * strideB + n];
    }
    if (tid < HID) Wss[tid] = Ws[tid];
    __syncthreads();

    const int cg = tid & 63;   // col group: cols [4*cg, 4*cg+3]
    const int rg = tid >> 6;   // row group: rows [4*rg, 4*rg+3]

    // k = 0..2 : real matmuls
    for (int k = 0; k < 3; k++) {
        const float4* Lk = reinterpret_cast<const float4*>(L + (long)k*HID*HID);
        const float4* Rk = reinterpret_cast<const float4*>(R + (long)k*HID*HID);

        float4 accL[4], accR[4];
        #pragma unroll
        for (int j = 0; j < 4; j++) {
            accL[j] = make_float4(0.f, 0.f, 0.f, 0.f);
            accR[j] = make_float4(0.f, 0.f, 0.f, 0.f);
        }

        for (int h = 0; h < HID; h += 4) {
            float4 a4[4], b4[4];
            #pragma unroll
            for (int j = 0; j < 4; j++) {
                a4[j] = *reinterpret_cast<const float4*>(&As[(rg*4 + j)*HID + h]);
                if (MODE != 1)
                    b4[j] = *reinterpret_cast<const float4*>(&Bs[(rg*4 + j)*HID + h]);
            }
            #pragma unroll
            for (int hh = 0; hh < 4; hh++) {
                float4 wl, wr;
                if (MODE != 1) wl = Lk[(h + hh)*64 + cg];
                wr = Rk[(h + hh)*64 + cg];
                #pragma unroll
                for (int j = 0; j < 4; j++) {
                    float av = reinterpret_cast<const float*>(&a4[j])[hh];
                    if (MODE == 0) {
                        float bv = reinterpret_cast<const float*>(&b4[j])[hh];
                        accL[j].x = fmaf(av, wl.x, accL[j].x);
                        accL[j].y = fmaf(av, wl.y, accL[j].y);
                        accL[j].z = fmaf(av, wl.z, accL[j].z);
                        accL[j].w = fmaf(av, wl.w, accL[j].w);
                        accL[j].x = fmaf(bv, wr.x, accL[j].x);
                        accL[j].y = fmaf(bv, wr.y, accL[j].y);
                        accL[j].z = fmaf(bv, wr.z, accL[j].z);
                        accL[j].w = fmaf(bv, wr.w, accL[j].w);
                    } else if (MODE == 1) {
                        accL[j].x = fmaf(av, wr.x, accL[j].x);
                        accL[j].y = fmaf(av, wr.y, accL[j].y);
                        accL[j].z = fmaf(av, wr.z, accL[j].z);
                        accL[j].w = fmaf(av, wr.w, accL[j].w);
                    } else {
                        float bv = reinterpret_cast<const float*>(&b4[j])[hh];
                        accL[j].x = fmaf(av, wl.x, accL[j].x);
                        accL[j].y = fmaf(av, wl.y, accL[j].y);
                        accL[j].z = fmaf(av, wl.z, accL[j].z);
                        accL[j].w = fmaf(av, wl.w, accL[j].w);
                        accR[j].x = fmaf(bv, wr.x, accR[j].x);
                        accR[j].y = fmaf(bv, wr.y, accR[j].y);
                        accR[j].z = fmaf(bv, wr.z, accR[j].z);
                        accR[j].w = fmaf(bv, wr.w, accR[j].w);
                    }
                }
            }
        }

        float4 bb = reinterpret_cast<const float4*>(bvec + k*HID)[cg];
        #pragma unroll
        for (int j = 0; j < 4; j++) {
            float4 c;
            if (MODE == 0) {
                c.x = accL[j].x + bb.x; c.y = accL[j].y + bb.y;
                c.z = accL[j].z + bb.z; c.w = accL[j].w + bb.w;
            } else if (MODE == 1) {
                c.x = 1.0f - (accL[j].x + bb.x); c.y = 1.0f - (accL[j].y + bb.y);
                c.z = 1.0f - (accL[j].z + bb.z); c.w = 1.0f - (accL[j].w + bb.w);
            } else {
                c.x = fmaf(accL[j].x, accR[j].x, bb.x);
                c.y = fmaf(accL[j].y, accR[j].y, bb.y);
                c.z = fmaf(accL[j].z, accR[j].z, bb.z);
                c.w = fmaf(accL[j].w, accR[j].w, bb.w);
            }
            *reinterpret_cast<float4*>(&Cs[k*MT*HID + (rg*4 + j)*HID + cg*4]) = c;
        }
    }

    // k = 3 : identity matrices -> elementwise
    {
        float4 b3 = reinterpret_cast<const float4*>(bvec + 3*HID)[cg];
        #pragma unroll
        for (int j = 0; j < 4; j++) {
            float4 a = *reinterpret_cast<const float4*>(&As[(rg*4 + j)*HID + cg*4]);
            float4 bq;
            if (MODE != 1) bq = *reinterpret_cast<const float4*>(&Bs[(rg*4 + j)*HID + cg*4]);
            float4 c;
            if (MODE == 0) {
                c.x = a.x + bq.x + b3.x; c.y = a.y + bq.y + b3.y;
                c.z = a.z + bq.z + b3.z; c.w = a.w + bq.w + b3.w;
            } else if (MODE == 1) {
                c.x = 1.0f - (a.x + b3.x); c.y = 1.0f - (a.y + b3.y);
                c.z = 1.0f - (a.z + b3.z); c.w = 1.0f - (a.w + b3.w);
            } else {
                c.x = fmaf(a.x, bq.x, b3.x); c.y = fmaf(a.y, bq.y, b3.y);
                c.z = fmaf(a.z, bq.z, b3.z); c.w = fmaf(a.w, bq.w, b3.w);
            }
            *reinterpret_cast<float4*>(&Cs[3*MT*HID + (rg*4 + j)*HID + cg*4]) = c;
        }
    }
    __syncthreads();

    // scores[k][m] = dot(Cs[k][m][:], Ws)  -- 128 warp-dot tasks across 16 warps
    {
        const int warp = tid >> 5, lane = tid & 31;
        for (int t = warp; t < 4*MT; t += 16) {
            int k = t >> 5, m = t & 31;
            const float* cr = &Cs[k*MT*HID + m*HID];
            float d = 0.f;
            #pragma unroll
            for (int n = lane; n < HID; n += 32) d = fmaf(cr[n], Wss[n], d);
            #pragma unroll
            for (int off = 16; off; off >>= 1) d += __shfl_down_sync(0xffffffffu, d, off);
            if (lane == 0) Ssc[t] = d;
        }
    }
    __syncthreads();

    // block-level score sums -> global accumulators (for idx/margin)
    if (tid < 4) {
        float ssum = 0.f;
        for (int m = 0; m < MT; m++) ssum += Ssc[tid*MT + m];
        atomicAdd(&s_acc[tid], ssum);
    }

    // per-row softmax combine + store
    #pragma unroll
    for (int j = 0; j < 4; j++) {
        int m = rg*4 + j;
        float s0 = Ssc[m], s1 = Ssc[32 + m], s2 = Ssc[64 + m], s3 = Ssc[96 + m];
        float mx = fmaxf(fmaxf(s0, s1), fmaxf(s2, s3));
        float e0 = expf(s0 - mx), e1 = expf(s1 - mx), e2 = expf(s2 - mx), e3 = expf(s3 - mx);
        float inv = 1.0f / (e0 + e1 + e2 + e3);
        float w0 = e0*inv, w1 = e1*inv, w2 = e2*inv, w3 = e3*inv;

        const float* c0 = &Cs[m*HID + cg*4];
        float4 v0 = *reinterpret_cast<const float4*>(c0);
        float4 v1 = *reinterpret_cast<const float4*>(c0 + 1*MT*HID);
        float4 v2 = *reinterpret_cast<const float4*>(c0 + 2*MT*HID);
        float4 v3 = *reinterpret_cast<const float4*>(c0 + 3*MT*HID);
        float ox = w0*v0.x + w1*v1.x + w2*v2.x + w3*v3.x;
        float oy = w0*v0.y + w1*v1.y + w2*v2.y + w3*v3.y;
        float oz = w0*v0.z + w1*v1.z + w2*v2.z + w3*v3.z;
        float ow = w0*v0.w + w1*v1.w + w2*v2.w + w3*v3.w;

        long ro = row0 + m;
        float* op = out0 + ro*stride0 + cg*4;
        op[0] = ox; op[1] = oy; op[2] = oz; op[3] = ow;
        if (out1) {
            float* op2 = out1 + ro*stride1 + cg*4;
            op2[0] = ox; op2[1] = oy; op2[2] = oz; op2[3] = ow;
        }
    }
}

// z1 = sigmoid(x@L0 + h@R0 + b0) -> slots 0 and 2 ; r = sigmoid(x@L1 + h@R1 + b1) -> slot 1
__global__ void __launch_bounds__(NTHR, 1)
z1r_kernel(const float* __restrict__ x, const float* __restrict__ h,
           const float* __restrict__ L, const float* __restrict__ R,
           const float* __restrict__ bvec, float* __restrict__ gnode)
{
    extern __shared__ float sm[];
    float* As = sm;
    float* Bs = As + MT*HID;

    const int tid = threadIdx.x;
    const long row0 = (long)blockIdx.x * MT;

    for (int idx = tid; idx < MT*HID; idx += NTHR) {
        int m = idx >> 8, n = idx & 255;
        As[idx] = x[(row0 + m)*HID + n];
        Bs[idx] = h[(row0 + m)*HID + n];
    }
    __syncthreads();

    const int cg = tid & 63;
    const int rg = tid >> 6;

    for (int k = 0; k < 2; k++) {
        const float4* Lk = reinterpret_cast<const float4*>(L + (long)k*HID*HID);
        const float4* Rk = reinterpret_cast<const float4*>(R + (long)k*HID*HID);
        float4 acc[4];
        #pragma unroll
        for (int j = 0; j < 4; j++) acc[j] = make_float4(0.f, 0.f, 0.f, 0.f);

        for (int hh0 = 0; hh0 < HID; hh0 += 4) {
            float4 a4[4], b4[4];
            #pragma unroll
            for (int j = 0; j < 4; j++) {
                a4[j] = *reinterpret_cast<const float4*>(&As[(rg*4 + j)*HID + hh0]);
                b4[j] = *reinterpret_cast<const float4*>(&Bs[(rg*4 + j)*HID + hh0]);
            }
            #pragma unroll
            for (int hh = 0; hh < 4; hh++) {
                float4 wl = Lk[(hh0 + hh)*64 + cg];
                float4 wr = Rk[(hh0 + hh)*64 + cg];
                #pragma unroll
                for (int j = 0; j < 4; j++) {
                    float av = reinterpret_cast<const float*>(&a4[j])[hh];
                    float bv = reinterpret_cast<const float*>(&b4[j])[hh];
                    acc[j].x = fmaf(av, wl.x, acc[j].x);
                    acc[j].y = fmaf(av, wl.y, acc[j].y);
                    acc[j].z = fmaf(av, wl.z, acc[j].z);
                    acc[j].w = fmaf(av, wl.w, acc[j].w);
                    acc[j].x = fmaf(bv, wr.x, acc[j].x);
                    acc[j].y = fmaf(bv, wr.y, acc[j].y);
                    acc[j].z = fmaf(bv, wr.z, acc[j].z);
                    acc[j].w = fmaf(bv, wr.w, acc[j].w);
                }
            }
        }

        float4 bb = reinterpret_cast<const float4*>(bvec + k*HID)[cg];
        #pragma unroll
        for (int j = 0; j < 4; j++) {
            float cx = sigmoidf_(acc[j].x + bb.x);
            float cy = sigmoidf_(acc[j].y + bb.y);
            float cz = sigmoidf_(acc[j].z + bb.z);
            float cw = sigmoidf_(acc[j].w + bb.w);
            long ro = row0 + rg*4 + j;
            float* op = gnode + ro*GN_STRIDE + k*HID + cg*4;   // slot k (0->z1, 1->r)
            op[0] = cx; op[1] = cy; op[2] = cz; op[3] = cw;
            if (k == 0) {                                      // z2 = z1 (slot 2)
                float* op2 = gnode + ro*GN_STRIDE + 2*HID + cg*4;
                op2[0] = cx; op2[1] = cy; op2[2] = cz; op2[3] = cw;
            }
        }
    }
}

__global__ void finalize_kernel(float* __restrict__ out) {
    if (threadIdx.x == 0 && blockIdx.x == 0) {
        float* gstr = out + OFF_GSTR;
        float* mg   = out + OFF_MARG;
        gstr[0] = 0.0f; gstr[1] = 1.0f; gstr[2] = 0.0f;
        for (int st = 0; st < 6; st++) {
            float s0 = g_s[st*4 + 0], s1 = g_s[st*4 + 1];
            float s2 = g_s[st*4 + 2], s3 = g_s[st*4 + 3];
            float s[4] = {s0, s1, s2, s3};
            int idx = 0; float best = s[0];
            #pragma unroll
            for (int i = 1; i < 4; i++) if (s[i] > best) { best = s[i]; idx = i; }
            float second = -INFINITY;
            #pragma unroll
            for (int i = 0; i < 4; i++) if (i != idx) second = fmaxf(second, s[i]);
            gstr[3 + st] = (float)idx;
            mg[st] = best - second;
        }
    }
}

extern "C" void kernel_launch(void* const* d_in, const int* in_sizes, int n_in,
                              void* d_out, int out_size)
{
    const float* x  = (const float*)d_in[0];
    const float* h  = (const float*)d_in[1];
    const float* L  = (const float*)d_in[2];
    const float* R  = (const float*)d_in[3];
    const float* b  = (const float*)d_in[4];
    const float* Ws = (const float*)d_in[5];
    float* out = (float*)d_out;
    float* gnode = out + OFF_GNODE;

    size_t smem = SMEM_FLOATS * sizeof(float);
    cudaFuncSetAttribute((const void*)z1r_kernel,
                         cudaFuncAttributeMaxDynamicSharedMemorySize, (int)smem);
    cudaFuncSetAttribute((const void*)stage_kernel<0>,
                         cudaFuncAttributeMaxDynamicSharedMemorySize, (int)smem);
    cudaFuncSetAttribute((const void*)stage_kernel<1>,
                         cudaFuncAttributeMaxDynamicSharedMemorySize, (int)smem);
    cudaFuncSetAttribute((const void*)stage_kernel<2>,
                         cudaFuncAttributeMaxDynamicSharedMemorySize, (int)smem);

    float* s_dev = nullptr;
    cudaGetSymbolAddress((void**)&s_dev, g_s);

    const int grid = BATCH / MT;   // 512

    zero_s_kernel<<<1, 32>>>();

    // z1 (slots 0,2), r (slot 1)
    z1r_kernel<<<grid, NTHR, smem>>>(x, h, L, R, b, gnode);

    // stage 1: rh = mixture(h@L + r@R + b) -> slot 3
    stage_kernel<0><<<grid, NTHR, smem>>>(h, (long)HID, gnode + 1*HID, (long)GN_STRIDE,
                                          L, R, b, Ws,
                                          gnode + 3*HID, (long)GN_STRIDE, nullptr, 0,
                                          s_dev + 0);
    // stage 2: h_tilde = mixture(x@L + rh@R + b) -> slot 4
    stage_kernel<0><<<grid, NTHR, smem>>>(x, (long)HID, gnode + 3*HID, (long)GN_STRIDE,
                                          L, R, b, Ws,
                                          gnode + 4*HID, (long)GN_STRIDE, nullptr, 0,
                                          s_dev + 4);
    // stage 3: oneMinusZ1 = mixture(1 - (z1@R + b)) -> slot 5
    stage_kernel<1><<<grid, NTHR, smem>>>(gnode + 0*HID, (long)GN_STRIDE, nullptr, 0,
                                          L, R, b, Ws,
                                          gnode + 5*HID, (long)GN_STRIDE, nullptr, 0,
                                          s_dev + 8);
    // stage 4: zh_tilde = mixture((h_tilde@L)*(oneMinusZ1@R) + b) -> slot 6
    stage_kernel<2><<<grid, NTHR, smem>>>(gnode + 4*HID, (long)GN_STRIDE,
                                          gnode + 5*HID, (long)GN_STRIDE,
                                          L, R, b, Ws,
                                          gnode + 6*HID, (long)GN_STRIDE, nullptr, 0,
                                          s_dev + 12);
    // stage 5: z2h = mixture((h@L)*(z2@R) + b) -> slot 7   (z2 == z1, slot 0)
    stage_kernel<2><<<grid, NTHR, smem>>>(h, (long)HID,
                                          gnode + 0*HID, (long)GN_STRIDE,
                                          L, R, b, Ws,
                                          gnode + 7*HID, (long)GN_STRIDE, nullptr, 0,
                                          s_dev + 16);
    // stage 6: h_next = mixture(zh_tilde@L + z2h@R + b) -> slot 8 + h_next output
    stage_kernel<0><<<grid, NTHR, smem>>>(gnode + 6*HID, (long)GN_STRIDE,
                                          gnode + 7*HID, (long)GN_STRIDE,
                                          L, R, b, Ws,
                                          gnode + 8*HID, (long)GN_STRIDE,
                                          out + OFF_HNEXT, (long)HID,
                                          s_dev + 20);

    finalize_kernel<<<1, 32>>>(out);
}

// round 3
// speedup vs baseline: 1.5971x; 1.0002x over previous
#include <cuda_runtime.h>
#include <math.h>

#define HID   256
#define BATCH 16384
#define LK    4
#define MT    32      // rows per block
#define NTHR  512

// ---- output layout (floats), assuming tuple flattened in order ----
#define OFF_HNEXT 0
#define OFF_GSTR  (BATCH*HID)                    // 4194304
#define OFF_GNODE (OFF_GSTR + 9)                 // 4194313 (mod 4 == 1 -> scalar stores)
#define OFF_MARG  (OFF_GNODE + (long)BATCH*9*HID)
#define GN_STRIDE (9*HID)

// per-stage score accumulators: 6 stages x 4 experts
__device__ float g_s[24];

__global__ void zero_s_kernel() {
    if (threadIdx.x < 24) g_s[threadIdx.x] = 0.0f;
}

// smem layout (floats): As[MT*HID], Bs[MT*HID], Cs[4*MT*HID], Wss[HID], Ssc[4*MT]
#define SMEM_FLOATS (MT*HID*2 + 4*MT*HID + HID + 4*MT + 32)

__device__ __forceinline__ float sigmoidf_(float v) {
    return 1.0f / (1.0f + expf(-v));
}

// MODE: 0 = LIN  (A@L[k] + B@R[k] + b)
//       1 = OMZ  (1 - (A@R[k] + b))
//       2 = MUL  ((A@L[k]) * (B@R[k]) + b)
template<int MODE>
__global__ void __launch_bounds__(NTHR, 1)
stage_kernel(const float* __restrict__ A, long strideA,
             const float* __restrict__ Bv, long strideB,
             const float* __restrict__ L, const float* __restrict__ R,
             const float* __restrict__ bvec, const float* __restrict__ Ws,
             float* __restrict__ out0, long stride0,
             float* __restrict__ out1, long stride1,
             float* __restrict__ s_acc)
{
    extern __shared__ float sm[];
    float* As  = sm;
    float* Bs  = As + MT*HID;
    float* Cs  = Bs + MT*HID;
    float* Wss = Cs + 4*MT*HID;
    float* Ssc = Wss + HID;

    const int tid  = threadIdx.x;
    const long row0 = (long)blockIdx.x * MT;

    // load input tiles (scalar: stage inputs from G_node region are 4B-misaligned for f4)
    for (int idx = tid; idx < MT*HID; idx += NTHR) {
        int m = idx >> 8, n = idx & 255;
        As[idx] = A[(row0 + m) * strideA + n];
        if (MODE != 1) Bs[idx] = Bv[(row0 + m) * strideB + n];
    }
    if (tid < HID) Wss[tid] = Ws[tid];
    __syncthreads();

    const int cg = tid & 63;   // col group: cols [4*cg, 4*cg+3]
    const int rg = tid >> 6;   // row group: rows [4*rg, 4*rg+3]

    // k = 0..2 : real matmuls
    for (int k = 0; k < 3; k++) {
        const float4* Lk = reinterpret_cast<const float4*>(L + (long)k*HID*HID);
        const float4* Rk = reinterpret_cast<const float4*>(R + (long)k*HID*HID);

        float4 accL[4], accR[4];
        #pragma unroll
        for (int j = 0; j < 4; j++) {
            accL[j] = make_float4(0.f, 0.f, 0.f, 0.f);
            accR[j] = make_float4(0.f, 0.f, 0.f, 0.f);
        }

        for (int h = 0; h < HID; h += 4) {
            float4 a4[4], b4[4];
            #pragma unroll
            for (int j = 0; j < 4; j++) {
                a4[j] = *reinterpret_cast<const float4*>(&As[(rg*4 + j)*HID + h]);
                if (MODE != 1)
                    b4[j] = *reinterpret_cast<const float4*>(&Bs[(rg*4 + j)*HID + h]);
            }
            #pragma unroll
            for (int hh = 0; hh < 4; hh++) {
                float4 wl, wr;
                if (MODE != 1) wl = Lk[(h + hh)*64 + cg];
                wr = Rk[(h + hh)*64 + cg];
                #pragma unroll
                for (int j = 0; j < 4; j++) {
                    float av = reinterpret_cast<const float*>(&a4[j])[hh];
                    if (MODE == 0) {
                        float bv = reinterpret_cast<const float*>(&b4[j])[hh];
                        accL[j].x = fmaf(av, wl.x, accL[j].x);
                        accL[j].y = fmaf(av, wl.y, accL[j].y);
                        accL[j].z = fmaf(av, wl.z, accL[j].z);
                        accL[j].w = fmaf(av, wl.w, accL[j].w);
                        accL[j].x = fmaf(bv, wr.x, accL[j].x);
                        accL[j].y = fmaf(bv, wr.y, accL[j].y);
                        accL[j].z = fmaf(bv, wr.z, accL[j].z);
                        accL[j].w = fmaf(bv, wr.w, accL[j].w);
                    } else if (MODE == 1) {
                        accL[j].x = fmaf(av, wr.x, accL[j].x);
                        accL[j].y = fmaf(av, wr.y, accL[j].y);
                        accL[j].z = fmaf(av, wr.z, accL[j].z);
                        accL[j].w = fmaf(av, wr.w, accL[j].w);
                    } else {
                        float bv = reinterpret_cast<const float*>(&b4[j])[hh];
                        accL[j].x = fmaf(av, wl.x, accL[j].x);
                        accL[j].y = fmaf(av, wl.y, accL[j].y);
                        accL[j].z = fmaf(av, wl.z, accL[j].z);
                        accL[j].w = fmaf(av, wl.w, accL[j].w);
                        accR[j].x = fmaf(bv, wr.x, accR[j].x);
                        accR[j].y = fmaf(bv, wr.y, accR[j].y);
                        accR[j].z = fmaf(bv, wr.z, accR[j].z);
                        accR[j].w = fmaf(bv, wr.w, accR[j].w);
                    }
                }
            }
        }

        float4 bb = reinterpret_cast<const float4*>(bvec + k*HID)[cg];
        #pragma unroll
        for (int j = 0; j < 4; j++) {
            float4 c;
            if (MODE == 0) {
                c.x = accL[j].x + bb.x; c.y = accL[j].y + bb.y;
                c.z = accL[j].z + bb.z; c.w = accL[j].w + bb.w;
            } else if (MODE == 1) {
                c.x = 1.0f - (accL[j].x + bb.x); c.y = 1.0f - (accL[j].y + bb.y);
                c.z = 1.0f - (accL[j].z + bb.z); c.w = 1.0f - (accL[j].w + bb.w);
            } else {
                c.x = fmaf(accL[j].x, accR[j].x, bb.x);
                c.y = fmaf(accL[j].y, accR[j].y, bb.y);
                c.z = fmaf(accL[j].z, accR[j].z, bb.z);
                c.w = fmaf(accL[j].w, accR[j].w, bb.w);
            }
            *reinterpret_cast<float4*>(&Cs[k*MT*HID + (rg*4 + j)*HID + cg*4]) = c;
        }
    }

    // k = 3 : identity matrices -> elementwise
    {
        float4 b3 = reinterpret_cast<const float4*>(bvec + 3*HID)[cg];
        #pragma unroll
        for (int j = 0; j < 4; j++) {
            float4 a = *reinterpret_cast<const float4*>(&As[(rg*4 + j)*HID + cg*4]);
            float4 bq;
            if (MODE != 1) bq = *reinterpret_cast<const float4*>(&Bs[(rg*4 + j)*HID + cg*4]);
            float4 c;
            if (MODE == 0) {
                c.x = a.x + bq.x + b3.x; c.y = a.y + bq.y + b3.y;
                c.z = a.z + bq.z + b3.z; c.w = a.w + bq.w + b3.w;
            } else if (MODE == 1) {
                c.x = 1.0f - (a.x + b3.x); c.y = 1.0f - (a.y + b3.y);
                c.z = 1.0f - (a.z + b3.z); c.w = 1.0f - (a.w + b3.w);
            } else {
                c.x = fmaf(a.x, bq.x, b3.x); c.y = fmaf(a.y, bq.y, b3.y);
                c.z = fmaf(a.z, bq.z, b3.z); c.w = fmaf(a.w, bq.w, b3.w);
            }
            *reinterpret_cast<float4*>(&Cs[3*MT*HID + (rg*4 + j)*HID + cg*4]) = c;
        }
    }
    __syncthreads();

    // scores[k][m] = dot(Cs[k][m][:], Ws)  -- 128 warp-dot tasks across 16 warps
    {
        const int warp = tid >> 5, lane = tid & 31;
        for (int t = warp; t < 4*MT; t += 16) {
            int k = t >> 5, m = t & 31;
            const float* cr = &Cs[k*MT*HID + m*HID];
            float d = 0.f;
            #pragma unroll
            for (int n = lane; n < HID; n += 32) d = fmaf(cr[n], Wss[n], d);
            #pragma unroll
            for (int off = 16; off; off >>= 1) d += __shfl_down_sync(0xffffffffu, d, off);
            if (lane == 0) Ssc[t] = d;
        }
    }
    __syncthreads();

    // block-level score sums -> global accumulators (for idx/margin)
    if (tid < 4) {
        float ssum = 0.f;
        for (int m = 0; m < MT; m++) ssum += Ssc[tid*MT + m];
        atomicAdd(&s_acc[tid], ssum);
    }

    // per-row softmax combine + store
    #pragma unroll
    for (int j = 0; j < 4; j++) {
        int m = rg*4 + j;
        float s0 = Ssc[m], s1 = Ssc[32 + m], s2 = Ssc[64 + m], s3 = Ssc[96 + m];
        float mx = fmaxf(fmaxf(s0, s1), fmaxf(s2, s3));
        float e0 = expf(s0 - mx), e1 = expf(s1 - mx), e2 = expf(s2 - mx), e3 = expf(s3 - mx);
        float inv = 1.0f / (e0 + e1 + e2 + e3);
        float w0 = e0*inv, w1 = e1*inv, w2 = e2*inv, w3 = e3*inv;

        const float* c0 = &Cs[m*HID + cg*4];
        float4 v0 = *reinterpret_cast<const float4*>(c0);
        float4 v1 = *reinterpret_cast<const float4*>(c0 + 1*MT*HID);
        float4 v2 = *reinterpret_cast<const float4*>(c0 + 2*MT*HID);
        float4 v3 = *reinterpret_cast<const float4*>(c0 + 3*MT*HID);
        float ox = w0*v0.x + w1*v1.x + w2*v2.x + w3*v3.x;
        float oy = w0*v0.y + w1*v1.y + w2*v2.y + w3*v3.y;
        float oz = w0*v0.z + w1*v1.z + w2*v2.z + w3*v3.z;
        float ow = w0*v0.w + w1*v1.w + w2*v2.w + w3*v3.w;

        long ro = row0 + m;
        float* op = out0 + ro*stride0 + cg*4;
        op[0] = ox; op[1] = oy; op[2] = oz; op[3] = ow;
        if (out1) {
            float* op2 = out1 + ro*stride1 + cg*4;
            op2[0] = ox; op2[1] = oy; op2[2] = oz; op2[3] = ow;
        }
    }
}

// z1 = sigmoid(x@L0 + h@R0 + b0) -> slots 0 and 2 ; r = sigmoid(x@L1 + h@R1 + b1) -> slot 1
__global__ void __launch_bounds__(NTHR, 1)
z1r_kernel(const float* __restrict__ x, const float* __restrict__ h,
           const float* __restrict__ L, const float* __restrict__ R,
           const float* __restrict__ bvec, float* __restrict__ gnode)
{
    extern __shared__ float sm[];
    float* As = sm;
    float* Bs = As + MT*HID;

    const int tid = threadIdx.x;
    const long row0 = (long)blockIdx.x * MT;

    for (int idx = tid; idx < MT*HID; idx += NTHR) {
        int m = idx >> 8, n = idx & 255;
        As[idx] = x[(row0 + m)*HID + n];
        Bs[idx] = h[(row0 + m)*HID + n];
    }
    __syncthreads();

    const int cg = tid & 63;
    const int rg = tid >> 6;

    for (int k = 0; k < 2; k++) {
        const float4* Lk = reinterpret_cast<const float4*>(L + (long)k*HID*HID);
        const float4* Rk = reinterpret_cast<const float4*>(R + (long)k*HID*HID);
        float4 acc[4];
        #pragma unroll
        for (int j = 0; j < 4; j++) acc[j] = make_float4(0.f, 0.f, 0.f, 0.f);

        for (int hh0 = 0; hh0 < HID; hh0 += 4) {
            float4 a4[4], b4[4];
            #pragma unroll
            for (int j = 0; j < 4; j++) {
                a4[j] = *reinterpret_cast<const float4*>(&As[(rg*4 + j)*HID + hh0]);
                b4[j] = *reinterpret_cast<const float4*>(&Bs[(rg*4 + j)*HID + hh0]);
            }
            #pragma unroll
            for (int hh = 0; hh < 4; hh++) {
                float4 wl = Lk[(hh0 + hh)*64 + cg];
                float4 wr = Rk[(hh0 + hh)*64 + cg];
                #pragma unroll
                for (int j = 0; j < 4; j++) {
                    float av = reinterpret_cast<const float*>(&a4[j])[hh];
                    float bv = reinterpret_cast<const float*>(&b4[j])[hh];
                    acc[j].x = fmaf(av, wl.x, acc[j].x);
                    acc[j].y = fmaf(av, wl.y, acc[j].y);
                    acc[j].z = fmaf(av, wl.z, acc[j].z);
                    acc[j].w = fmaf(av, wl.w, acc[j].w);
                    acc[j].x = fmaf(bv, wr.x, acc[j].x);
                    acc[j].y = fmaf(bv, wr.y, acc[j].y);
                    acc[j].z = fmaf(bv, wr.z, acc[j].z);
                    acc[j].w = fmaf(bv, wr.w, acc[j].w);
                }
            }
        }

        float4 bb = reinterpret_cast<const float4*>(bvec + k*HID)[cg];
        #pragma unroll
        for (int j = 0; j < 4; j++) {
            float cx = sigmoidf_(acc[j].x + bb.x);
            float cy = sigmoidf_(acc[j].y + bb.y);
            float cz = sigmoidf_(acc[j].z + bb.z);
            float cw = sigmoidf_(acc[j].w + bb.w);
            long ro = row0 + rg*4 + j;
            float* op = gnode + ro*GN_STRIDE + k*HID + cg*4;   // slot k (0->z1, 1->r)
            op[0] = cx; op[1] = cy; op[2] = cz; op[3] = cw;
            if (k == 0) {                                      // z2 = z1 (slot 2)
                float* op2 = gnode + ro*GN_STRIDE + 2*HID + cg*4;
                op2[0] = cx; op2[1] = cy; op2[2] = cz; op2[3] = cw;
            }
        }
    }
}

__global__ void finalize_kernel(float* __restrict__ out) {
    if (threadIdx.x == 0 && blockIdx.x == 0) {
        float* gstr = out + OFF_GSTR;
        float* mg   = out + OFF_MARG;
        gstr[0] = 0.0f; gstr[1] = 1.0f; gstr[2] = 0.0f;
        for (int st = 0; st < 6; st++) {
            float s0 = g_s[st*4 + 0], s1 = g_s[st*4 + 1];
            float s2 = g_s[st*4 + 2], s3 = g_s[st*4 + 3];
            float s[4] = {s0, s1, s2, s3};
            int idx = 0; float best = s[0];
            #pragma unroll
            for (int i = 1; i < 4; i++) if (s[i] > best) { best = s[i]; idx = i; }
            float second = -INFINITY;
            #pragma unroll
            for (int i = 0; i < 4; i++) if (i != idx) second = fmaxf(second, s[i]);
            gstr[3 + st] = (float)idx;
            mg[st] = best - second;
        }
    }
}

extern "C" void kernel_launch(void* const* d_in, const int* in_sizes, int n_in,
                              void* d_out, int out_size)
{
    const float* x  = (const float*)d_in[0];
    const float* h  = (const float*)d_in[1];
    const float* L  = (const float*)d_in[2];
    const float* R  = (const float*)d_in[3];
    const float* b  = (const float*)d_in[4];
    const float* Ws = (const float*)d_in[5];
    float* out = (float*)d_out;
    float* gnode = out + OFF_GNODE;

    size_t smem = SMEM_FLOATS * sizeof(float);
    cudaFuncSetAttribute((const void*)z1r_kernel,
                         cudaFuncAttributeMaxDynamicSharedMemorySize, (int)smem);
    cudaFuncSetAttribute((const void*)stage_kernel<0>,
                         cudaFuncAttributeMaxDynamicSharedMemorySize, (int)smem);
    cudaFuncSetAttribute((const void*)stage_kernel<1>,
                         cudaFuncAttributeMaxDynamicSharedMemorySize, (int)smem);
    cudaFuncSetAttribute((const void*)stage_kernel<2>,
                         cudaFuncAttributeMaxDynamicSharedMemorySize, (int)smem);

    float* s_dev = nullptr;
    cudaGetSymbolAddress((void**)&s_dev, g_s);

    const int grid = BATCH / MT;   // 512

    zero_s_kernel<<<1, 32>>>();

    // z1 (slots 0,2), r (slot 1)
    z1r_kernel<<<grid, NTHR, smem>>>(x, h, L, R, b, gnode);

    // stage 1: rh = mixture(h@L + r@R + b) -> slot 3
    stage_kernel<0><<<grid, NTHR, smem>>>(h, (long)HID, gnode + 1*HID, (long)GN_STRIDE,
                                          L, R, b, Ws,
                                          gnode + 3*HID, (long)GN_STRIDE, nullptr, 0,
                                          s_dev + 0);
    // stage 2: h_tilde = mixture(x@L + rh@R + b) -> slot 4
    stage_kernel<0><<<grid, NTHR, smem>>>(x, (long)HID, gnode + 3*HID, (long)GN_STRIDE,
                                          L, R, b, Ws,
                                          gnode + 4*HID, (long)GN_STRIDE, nullptr, 0,
                                          s_dev + 4);
    // stage 3: oneMinusZ1 = mixture(1 - (z1@R + b)) -> slot 5
    stage_kernel<1><<<grid, NTHR, smem>>>(gnode + 0*HID, (long)GN_STRIDE, nullptr, 0,
                                          L, R, b, Ws,
                                          gnode + 5*HID, (long)GN_STRIDE, nullptr, 0,
                                          s_dev + 8);
    // stage 4: zh_tilde = mixture((h_tilde@L)*(oneMinusZ1@R) + b) -> slot 6
    stage_kernel<2><<<grid, NTHR, smem>>>(gnode + 4*HID, (long)GN_STRIDE,
                                          gnode + 5*HID, (long)GN_STRIDE,
                                          L, R, b, Ws,
                                          gnode + 6*HID, (long)GN_STRIDE, nullptr, 0,
                                          s_dev + 12);
    // stage 5: z2h = mixture((h@L)*(z2@R) + b) -> slot 7   (z2 == z1, slot 0)
    stage_kernel<2><<<grid, NTHR, smem>>>(h, (long)HID,
                                          gnode + 0*HID, (long)GN_STRIDE,
                                          L, R, b, Ws,
                                          gnode + 7*HID, (long)GN_STRIDE, nullptr, 0,
                                          s_dev + 16);
    // stage 6: h_next = mixture(zh_tilde@L + z2h@R + b) -> slot 8 + h_next output
    stage_kernel<0><<<grid, NTHR, smem>>>(gnode + 6*HID, (long)GN_STRIDE,
                                          gnode + 7*HID, (long)GN_STRIDE,
                                          L, R, b, Ws,
                                          gnode + 8*HID, (long)GN_STRIDE,
                                          out + OFF_HNEXT, (long)HID,
                                          s_dev + 20);

    finalize_kernel<<<1, 32>>>(out);
}

// round 5
// speedup vs baseline: 3.7430x; 2.3436x over previous
#include <cuda_runtime.h>
#include <cuda_bf16.h>
#include <stdint.h>
#include <math.h>

#define HID   256
#define BATCH 16384

// ---- output layout (floats) ----
#define OFF_HNEXT 0
#define OFF_GSTR  (BATCH*HID)
#define OFF_GNODE (OFF_GSTR + 9)
#define OFF_MARG  (OFF_GNODE + (long)BATCH*9*HID)
#define GN_STRIDE (9*HID)

// ---- static device scratch ----
// activations (bf16 hi/lo splits, row-major [BATCH][HID]):
// 0:x 1:h 2:z1 3:r 4:rh 5:h_tilde 6:omz 7:zh_tilde 8:z2h
__device__ __align__(16) __nv_bfloat16 g_act[9][2][(size_t)BATCH*HID];
// weight tiles [n(64)][kk(64)] bf16 (i.e. W^T): [e][mat][sp][nt][ch]
__device__ __align__(16) __nv_bfloat16 g_w[3*2*2*4*4*4096];
#define W_IDX(k,mat,sp,nt,ch) ((((((size_t)(k)*2+(mat))*2+(sp))*4+(nt))*4+(ch))*4096)
// candidates (pre-bias) [row][e 0..2][256] fp32
__device__ __align__(16) float g_cand[(size_t)BATCH*3*HID];
__device__ float g_s[24];

// ---- helpers ----
__device__ __forceinline__ uint32_t smem_u32(const void* p) {
    uint32_t a;
    asm("{ .reg .u64 t; cvta.to.shared.u64 t, %1; cvt.u32.u64 %0, t; }" : "=r"(a) : "l"(p));
    return a;
}
__device__ __forceinline__ void cpasync16(uint32_t dst, const void* src) {
    asm volatile("cp.async.cg.shared.global [%0], [%1], 16;" :: "r"(dst), "l"(src));
}
#define CP_COMMIT() asm volatile("cp.async.commit_group;" ::: "memory")
#define CP_WAIT(n)  asm volatile("cp.async.wait_group %0;" :: "n"(n) : "memory")

__device__ __forceinline__ void ldsm4(uint32_t* r, uint32_t addr) {
    asm volatile("ldmatrix.sync.aligned.m8n8.x4.shared.b16 {%0,%1,%2,%3}, [%4];"
        : "=r"(r[0]), "=r"(r[1]), "=r"(r[2]), "=r"(r[3]) : "r"(addr));
}
__device__ __forceinline__ void mma16816(float* c, const uint32_t* a, uint32_t b0, uint32_t b1) {
    asm volatile("mma.sync.aligned.m16n8k16.row.col.f32.bf16.bf16.f32 "
        "{%0,%1,%2,%3}, {%4,%5,%6,%7}, {%8,%9}, {%0,%1,%2,%3};"
        : "+f"(c[0]), "+f"(c[1]), "+f"(c[2]), "+f"(c[3])
        : "r"(a[0]), "r"(a[1]), "r"(a[2]), "r"(a[3]), "r"(b0), "r"(b1));
}
__device__ __forceinline__ void split_bf(float v, __nv_bfloat16& hi, __nv_bfloat16& lo) {
    hi = __float2bfloat16(v);
    lo = __float2bfloat16(v - __bfloat162float(hi));
}
__device__ __forceinline__ uint32_t pack2(__nv_bfloat16 a, __nv_bfloat16 b) {
    __nv_bfloat162 t; t.x = a; t.y = b;
    return *reinterpret_cast<uint32_t*>(&t);
}
// swizzled byte offset within a [rows][64 bf16] tile (128B rows)
__device__ __forceinline__ int swz(int r, int cB) { return (r*128 + cB) ^ ((r & 7) << 4); }

__global__ void zero_s_kernel() { if (threadIdx.x < 24) g_s[threadIdx.x] = 0.0f; }

// split + transpose weights into [n][kk] tiles
__global__ void __launch_bounds__(256) wprep_kernel(const float* __restrict__ L, const float* __restrict__ R) {
    int b = blockIdx.x;
    int ch = b & 3, nt = (b >> 2) & 3, mat = (b >> 4) & 1, k = b >> 5;
    const float* W = (mat ? R : L) + (size_t)k*HID*HID;
    __nv_bfloat16* th = g_w + W_IDX(k, mat, 0, nt, ch);
    __nv_bfloat16* tl = g_w + W_IDX(k, mat, 1, nt, ch);
    for (int e = threadIdx.x; e < 4096; e += 256) {
        int n = e >> 6, kk = e & 63;
        float w = W[(size_t)(ch*64 + kk)*HID + nt*64 + n];
        __nv_bfloat16 hi, lo; split_bf(w, hi, lo);
        th[n*64 + kk] = hi; tl[n*64 + kk] = lo;
    }
}

// split x,h into g_act[0], g_act[1]
__global__ void __launch_bounds__(256) xconv_kernel(const float* __restrict__ x, const float* __restrict__ h) {
    size_t i = (size_t)blockIdx.x*256 + threadIdx.x;
    if (i >= (size_t)BATCH*HID/4) return;
    #pragma unroll
    for (int t = 0; t < 2; t++) {
        const float4 v = reinterpret_cast<const float4*>(t ? h : x)[i];
        __nv_bfloat16 h0,h1,h2,h3,l0,l1,l2,l3;
        split_bf(v.x,h0,l0); split_bf(v.y,h1,l1); split_bf(v.z,h2,l2); split_bf(v.w,h3,l3);
        uint2 uh; uh.x = pack2(h0,h1); uh.y = pack2(h2,h3);
        uint2 ul; ul.x = pack2(l0,l1); ul.y = pack2(l2,l3);
        reinterpret_cast<uint2*>(&g_act[t][0][0])[i] = uh;
        reinterpret_cast<uint2*>(&g_act[t][1][0])[i] = ul;
    }
}

// one 64-k chunk of HMMA accumulation
__device__ __forceinline__ void compute_chunk(float (&acc)[64], uint32_t XS, uint32_t WS,
                                              int lane, int wm, int wn) {
    const int kh  = (lane >> 4) * 16;           // byte offset of k-half
    const int rA  = wm*64 + (lane & 15);
    const int nB0 = wn*32 + (lane & 15);
    #pragma unroll
    for (int ks = 0; ks < 4; ks++) {
        const int cB = ks*32 + kh;
        uint32_t B0[4], B1[4];
        ldsm4(B0, WS + swz(nB0,      cB));
        ldsm4(B1, WS + swz(nB0 + 16, cB));
        #pragma unroll
        for (int fm = 0; fm < 4; fm++) {
            uint32_t A[4];
            ldsm4(A, XS + swz(rA + fm*16, cB));
            mma16816(&acc[(fm*4+0)*4], A, B0[0], B0[2]);
            mma16816(&acc[(fm*4+1)*4], A, B0[1], B0[3]);
            mma16816(&acc[(fm*4+2)*4], A, B1[0], B1[2]);
            mma16816(&acc[(fm*4+3)*4], A, B1[1], B1[3]);
        }
    }
}

// MODE: 0 LIN (A@L_e + B@R_e) -> cand
//       1 OMZ (A@R_e)         -> cand
//       2 MUL (A@L_e)*(B@R_e) -> cand
//       3 Z1R (A@L_e + B@R_e, sigmoid) -> gnode slots + act splits   (e in {0,1})
// smem (dyn 64KB): X bufs @0,@16384 ; W bufs @32768,@49152  (each 128 rows x 64 bf16, swizzled)
template<int MODE>
__global__ void __launch_bounds__(256, (MODE==2) ? 1 : 2)
mma_stage(const __nv_bfloat16* __restrict__ aHi, const __nv_bfloat16* __restrict__ aLo,
          const __nv_bfloat16* __restrict__ bHi, const __nv_bfloat16* __restrict__ bLo,
          const float* __restrict__ bvec, float* __restrict__ gnode)
{
    extern __shared__ char smem[];
    const uint32_t sb = smem_u32(smem);
    const int tid = threadIdx.x, lane = tid & 31, warp = tid >> 5;
    const int wm = warp >> 2, wn = warp & 3;
    const int mtile = blockIdx.x, nt = blockIdx.y, e = blockIdx.z;
    const int NIT = ((MODE == 1) ? 1 : 2) * 12;

    float accA[64];
    float accB[64];
    #pragma unroll
    for (int i = 0; i < 64; i++) accA[i] = 0.0f;
    if (MODE == 2) {
        #pragma unroll
        for (int i = 0; i < 64; i++) accB[i] = 0.0f;
    }

    // ---- async load of iteration it into buffer buf ----
    auto load_iter = [&](int it, int buf) {
        const int op = it / 12, rem = it % 12, p = rem >> 2, ch = rem & 3;
        const int xs = (p == 2), ws = (p == 1);
        const int mat = (MODE == 1) ? 1 : op;
        const __nv_bfloat16* xp = op ? (xs ? bLo : bHi) : (xs ? aLo : aHi);
        const uint32_t xbase = sb + buf*16384;
        #pragma unroll
        for (int q = 0; q < 4; q++) {
            int s = tid + q*256;
            int r = s >> 3, sg = s & 7;
            cpasync16(xbase + swz(r, sg*16),
                      xp + (size_t)(mtile*128 + r)*HID + ch*64 + sg*8);
        }
        const uint32_t wbase = sb + 32768 + buf*16384;
        #pragma unroll
        for (int q = 0; q < 4; q++) {
            int s = tid + q*256;
            int n = s >> 3, sg = s & 7;
            int ng = nt*128 + n;
            cpasync16(wbase + swz(n, sg*16),
                      g_w + W_IDX(e, mat, ws, (ng >> 6), ch) + (ng & 63)*64 + sg*8);
        }
    };

    load_iter(0, 0); CP_COMMIT();
    for (int it = 0; it < NIT; it++) {
        if (it + 1 < NIT) { load_iter(it + 1, (it + 1) & 1); CP_COMMIT(); CP_WAIT(1); }
        else              { CP_WAIT(0); }
        __syncthreads();
        const uint32_t XS = sb + (it & 1)*16384;
        const uint32_t WS = sb + 32768 + (it & 1)*16384;
        if (MODE == 2 && it >= 12) compute_chunk(accB, XS, WS, lane, wm, wn);
        else                       compute_chunk(accA, XS, WS, lane, wm, wn);
        __syncthreads();
    }

    // ---- epilogue ----
    const int r0 = mtile*128 + wm*64 + (lane >> 2);
    const int c0 = nt*128 + wn*32 + (lane & 3)*2;
    if (MODE == 3) {
        #pragma unroll
        for (int fm = 0; fm < 4; fm++)
        #pragma unroll
        for (int fn = 0; fn < 4; fn++)
        #pragma unroll
        for (int h2 = 0; h2 < 2; h2++) {
            const int row = r0 + fm*16 + h2*8;
            const int col = c0 + fn*8;
            #pragma unroll
            for (int j = 0; j < 2; j++) {
                float v = accA[(fm*4+fn)*4 + h2*2 + j] + bvec[e*HID + col + j];
                float z = 1.0f / (1.0f + expf(-v));
                gnode[(size_t)row*GN_STRIDE + e*HID + col + j] = z;
                if (e == 0) gnode[(size_t)row*GN_STRIDE + 2*HID + col + j] = z;
                __nv_bfloat16 hi, lo; split_bf(z, hi, lo);
                g_act[2 + e][0][(size_t)row*HID + col + j] = hi;
                g_act[2 + e][1][(size_t)row*HID + col + j] = lo;
            }
        }
    } else {
        #pragma unroll
        for (int fm = 0; fm < 4; fm++)
        #pragma unroll
        for (int fn = 0; fn < 4; fn++)
        #pragma unroll
        for (int h2 = 0; h2 < 2; h2++) {
            const int row = r0 + fm*16 + h2*8;
            const int col = c0 + fn*8;
            const int ix = (fm*4+fn)*4 + h2*2;
            float v0 = accA[ix], v1 = accA[ix + 1];
            if (MODE == 2) { v0 *= accB[ix]; v1 *= accB[ix + 1]; }
            float2 st; st.x = v0; st.y = v1;
            *reinterpret_cast<float2*>(&g_cand[((size_t)row*3 + e)*HID + col]) = st;
        }
    }
}

// per-row mixture: bias + k=3 candidate (identity weights) + softmax combine + outputs + next-stage splits
template<int MODE>
__global__ void __launch_bounds__(256)
mixture_kernel(const float* __restrict__ A, long sA,
               const float* __restrict__ Bv, long sB,
               const float* __restrict__ bvec, const float* __restrict__ Ws,
               float* __restrict__ outSlot, float* __restrict__ out2,
               __nv_bfloat16* __restrict__ actHi, __nv_bfloat16* __restrict__ actLo,
               float* __restrict__ s_acc)
{
    __shared__ float ss[4];
    const int tid = threadIdx.x, rl = tid >> 5, lane = tid & 31;
    const long row = (long)blockIdx.x*8 + rl;
    const int c0 = lane*8;
    if (tid < 4) ss[tid] = 0.0f;
    __syncthreads();

    float cf[4][8], w8[8];
    #pragma unroll
    for (int j = 0; j < 8; j++) w8[j] = Ws[c0 + j];

    #pragma unroll
    for (int k = 0; k < 3; k++) {
        const float* cp = g_cand + ((size_t)row*3 + k)*HID + c0;
        float4 v0 = reinterpret_cast<const float4*>(cp)[0];
        float4 v1 = reinterpret_cast<const float4*>(cp)[1];
        float vv[8] = {v0.x, v0.y, v0.z, v0.w, v1.x, v1.y, v1.z, v1.w};
        #pragma unroll
        for (int j = 0; j < 8; j++) {
            float t = vv[j] + bvec[k*HID + c0 + j];
            cf[k][j] = (MODE == 1) ? (1.0f - t) : t;
        }
    }
    #pragma unroll
    for (int j = 0; j < 8; j++) {
        float a  = A[row*sA + c0 + j];
        float b3 = bvec[3*HID + c0 + j];
        if (MODE == 0)      cf[3][j] = a + Bv[row*sB + c0 + j] + b3;
        else if (MODE == 1) cf[3][j] = 1.0f - (a + b3);
        else                cf[3][j] = a * Bv[row*sB + c0 + j] + b3;
    }
    float d[4];
    #pragma unroll
    for (int k = 0; k < 4; k++) {
        float t = 0.f;
        #pragma unroll
        for (int j = 0; j < 8; j++) t = fmaf(cf[k][j], w8[j], t);
        #pragma unroll
        for (int off = 16; off; off >>= 1) t += __shfl_xor_sync(0xffffffffu, t, off);
        d[k] = t;
    }
    if (lane == 0) {
        atomicAdd(&ss[0], d[0]); atomicAdd(&ss[1], d[1]);
        atomicAdd(&ss[2], d[2]); atomicAdd(&ss[3], d[3]);
    }
    float mx = fmaxf(fmaxf(d[0], d[1]), fmaxf(d[2], d[3]));
    float e0 = expf(d[0]-mx), e1 = expf(d[1]-mx), e2 = expf(d[2]-mx), e3 = expf(d[3]-mx);
    float inv = 1.0f / (e0 + e1 + e2 + e3);
    float w0 = e0*inv, w1 = e1*inv, w2 = e2*inv, w3 = e3*inv;

    float o[8];
    #pragma unroll
    for (int j = 0; j < 8; j++)
        o[j] = w0*cf[0][j] + w1*cf[1][j] + w2*cf[2][j] + w3*cf[3][j];

    float* os = outSlot + row*GN_STRIDE + c0;
    #pragma unroll
    for (int j = 0; j < 8; j++) os[j] = o[j];
    if (out2) {
        float4 u0 = make_float4(o[0], o[1], o[2], o[3]);
        float4 u1 = make_float4(o[4], o[5], o[6], o[7]);
        reinterpret_cast<float4*>(out2 + row*HID + c0)[0] = u0;
        reinterpret_cast<float4*>(out2 + row*HID + c0)[1] = u1;
    }
    if (actHi) {
        __nv_bfloat16 hi[8], lo[8];
        #pragma unroll
        for (int j = 0; j < 8; j++) split_bf(o[j], hi[j], lo[j]);
        uint4 uh, ul;
        uh.x = pack2(hi[0],hi[1]); uh.y = pack2(hi[2],hi[3]); uh.z = pack2(hi[4],hi[5]); uh.w = pack2(hi[6],hi[7]);
        ul.x = pack2(lo[0],lo[1]); ul.y = pack2(lo[2],lo[3]); ul.z = pack2(lo[4],lo[5]); ul.w = pack2(lo[6],lo[7]);
        *reinterpret_cast<uint4*>(actHi + row*HID + c0) = uh;
        *reinterpret_cast<uint4*>(actLo + row*HID + c0) = ul;
    }
    __syncthreads();
    if (tid < 4) atomicAdd(&s_acc[tid], ss[tid]);
}

__global__ void finalize_kernel(float* __restrict__ out) {
    if (threadIdx.x == 0 && blockIdx.x == 0) {
        float* gstr = out + OFF_GSTR;
        float* mg   = out + OFF_MARG;
        gstr[0] = 0.0f; gstr[1] = 1.0f; gstr[2] = 0.0f;
        for (int st = 0; st < 6; st++) {
            float s[4] = {g_s[st*4+0], g_s[st*4+1], g_s[st*4+2], g_s[st*4+3]};
            int idx = 0; float best = s[0];
            #pragma unroll
            for (int i = 1; i < 4; i++) if (s[i] > best) { best = s[i]; idx = i; }
            float second = -INFINITY;
            #pragma unroll
            for (int i = 0; i < 4; i++) if (i != idx) second = fmaxf(second, s[i]);
            gstr[3 + st] = (float)idx;
            mg[st] = best - second;
        }
    }
}

extern "C" void kernel_launch(void* const* d_in, const int* in_sizes, int n_in,
                              void* d_out, int out_size)
{
    const float* x  = (const float*)d_in[0];
    const float* h  = (const float*)d_in[1];
    const float* L  = (const float*)d_in[2];
    const float* R  = (const float*)d_in[3];
    const float* b  = (const float*)d_in[4];
    const float* Ws = (const float*)d_in[5];
    float* out = (float*)d_out;
    float* gnode = out + OFF_GNODE;

    const int SMEM = 65536;
    cudaFuncSetAttribute((const void*)mma_stage<0>, cudaFuncAttributeMaxDynamicSharedMemorySize, SMEM);
    cudaFuncSetAttribute((const void*)mma_stage<1>, cudaFuncAttributeMaxDynamicSharedMemorySize, SMEM);
    cudaFuncSetAttribute((const void*)mma_stage<2>, cudaFuncAttributeMaxDynamicSharedMemorySize, SMEM);
    cudaFuncSetAttribute((const void*)mma_stage<3>, cudaFuncAttributeMaxDynamicSharedMemorySize, SMEM);

    float* s_dev = nullptr;
    cudaGetSymbolAddress((void**)&s_dev, g_s);
    __nv_bfloat16* actB = nullptr;
    cudaGetSymbolAddress((void**)&actB, g_act);
    auto act = [&](int t, int sp) { return actB + ((size_t)t*2 + sp)*((size_t)BATCH*HID); };

    zero_s_kernel<<<1, 32>>>();
    wprep_kernel<<<96, 256>>>(L, R);
    xconv_kernel<<<(BATCH*HID/4 + 255)/256, 256>>>(x, h);

    const dim3 G3(128, 2, 3), G2(128, 2, 2);
    const int GM = BATCH/8;   // 2048

    // z1 (slots 0,2) + r (slot 1), sigmoid epilogue, splits -> act2 (z1), act3 (r)
    mma_stage<3><<<G2, 256, SMEM>>>(act(0,0), act(0,1), act(1,0), act(1,1), b, gnode);

    // s1: rh = mix(h@L + r@R + b) -> slot3, act4
    mma_stage<0><<<G3, 256, SMEM>>>(act(1,0), act(1,1), act(3,0), act(3,1), nullptr, nullptr);
    mixture_kernel<0><<<GM, 256>>>(h, (long)HID, gnode + 1*HID, (long)GN_STRIDE, b, Ws,
                                   gnode + 3*HID, nullptr, act(4,0), act(4,1), s_dev + 0);
    // s2: h_tilde = mix(x@L + rh@R + b) -> slot4, act5
    mma_stage<0><<<G3, 256, SMEM>>>(act(0,0), act(0,1), act(4,0), act(4,1), nullptr, nullptr);
    mixture_kernel<0><<<GM, 256>>>(x, (long)HID, gnode + 3*HID, (long)GN_STRIDE, b, Ws,
                                   gnode + 4*HID, nullptr, act(5,0), act(5,1), s_dev + 4);
    // s3: omz = mix(1 - (z1@R + b)) -> slot5, act6
    mma_stage<1><<<G3, 256, SMEM>>>(act(2,0), act(2,1), nullptr, nullptr, nullptr, nullptr);
    mixture_kernel<1><<<GM, 256>>>(gnode + 0*HID, (long)GN_STRIDE, nullptr, 0, b, Ws,
                                   gnode + 5*HID, nullptr, act(6,0), act(6,1), s_dev + 8);
    // s4: zh_tilde = mix((h_tilde@L)*(omz@R) + b) -> slot6, act7
    mma_stage<2><<<G3, 256, SMEM>>>(act(5,0), act(5,1), act(6,0), act(6,1), nullptr, nullptr);
    mixture_kernel<2><<<GM, 256>>>(gnode + 4*HID, (long)GN_STRIDE, gnode + 5*HID, (long)GN_STRIDE, b, Ws,
                                   gnode + 6*HID, nullptr, act(7,0), act(7,1), s_dev + 12);
    // s5: z2h = mix((h@L)*(z1@R) + b) -> slot7, act8
    mma_stage<2><<<G3, 256, SMEM>>>(act(1,0), act(1,1), act(2,0), act(2,1), nullptr, nullptr);
    mixture_kernel<2><<<GM, 256>>>(h, (long)HID, gnode + 0*HID, (long)GN_STRIDE, b, Ws,
                                   gnode + 7*HID, nullptr, act(8,0), act(8,1), s_dev + 16);
    // s6: h_next = mix(zh@L + z2h@R + b) -> slot8 + h_next output
    mma_stage<0><<<G3, 256, SMEM>>>(act(7,0), act(7,1), act(8,0), act(8,1), nullptr, nullptr);
    mixture_kernel<0><<<GM, 256>>>(gnode + 6*HID, (long)GN_STRIDE, gnode + 7*HID, (long)GN_STRIDE, b, Ws,
                                   gnode + 8*HID, out + OFF_HNEXT, nullptr, nullptr, s_dev + 20);

    finalize_kernel<<<1, 32>>>(out);
}

// round 6
// speedup vs baseline: 3.7551x; 1.0032x over previous
#include <cuda_runtime.h>
#include <cuda_bf16.h>
#include <stdint.h>
#include <math.h>

#define HID   256
#define BATCH 16384

// ---- output layout (floats) ----
#define OFF_HNEXT 0
#define OFF_GSTR  (BATCH*HID)
#define OFF_GNODE (OFF_GSTR + 9)
#define OFF_MARG  (OFF_GNODE + (long)BATCH*9*HID)
#define GN_STRIDE (9*HID)

// ---- static device scratch ----
// activations (bf16 hi/lo splits, row-major [BATCH][HID]):
// 0:x 1:h 2:z1 3:r 4:rh 5:h_tilde 6:omz 7:zh_tilde 8:z2h
__device__ __align__(16) __nv_bfloat16 g_act[9][2][(size_t)BATCH*HID];
// weight tiles [n(64)][kk(64)] bf16 (i.e. W^T): [e][mat][sp][nt][ch]
__device__ __align__(16) __nv_bfloat16 g_w[3*2*2*4*4*4096];
#define W_IDX(k,mat,sp,nt,ch) ((((((size_t)(k)*2+(mat))*2+(sp))*4+(nt))*4+(ch))*4096)
// candidates (pre-bias) [row][e 0..2][256] fp32
__device__ __align__(16) float g_cand[(size_t)BATCH*3*HID];
__device__ float g_s[24];

// ---- helpers ----
__device__ __forceinline__ uint32_t smem_u32(const void* p) {
    uint32_t a;
    asm("{ .reg .u64 t; cvta.to.shared.u64 t, %1; cvt.u32.u64 %0, t; }" : "=r"(a) : "l"(p));
    return a;
}
__device__ __forceinline__ void cpasync16(uint32_t dst, const void* src) {
    asm volatile("cp.async.cg.shared.global [%0], [%1], 16;" :: "r"(dst), "l"(src));
}
#define CP_COMMIT() asm volatile("cp.async.commit_group;" ::: "memory")
#define CP_WAIT(n)  asm volatile("cp.async.wait_group %0;" :: "n"(n) : "memory")

__device__ __forceinline__ void ldsm4(uint32_t* r, uint32_t addr) {
    asm volatile("ldmatrix.sync.aligned.m8n8.x4.shared.b16 {%0,%1,%2,%3}, [%4];"
        : "=r"(r[0]), "=r"(r[1]), "=r"(r[2]), "=r"(r[3]) : "r"(addr));
}
__device__ __forceinline__ void mma16816(float* c, const uint32_t* a, uint32_t b0, uint32_t b1) {
    asm volatile("mma.sync.aligned.m16n8k16.row.col.f32.bf16.bf16.f32 "
        "{%0,%1,%2,%3}, {%4,%5,%6,%7}, {%8,%9}, {%0,%1,%2,%3};"
        : "+f"(c[0]), "+f"(c[1]), "+f"(c[2]), "+f"(c[3])
        : "r"(a[0]), "r"(a[1]), "r"(a[2]), "r"(a[3]), "r"(b0), "r"(b1));
}
__device__ __forceinline__ void split_bf(float v, __nv_bfloat16& hi, __nv_bfloat16& lo) {
    hi = __float2bfloat16(v);
    lo = __float2bfloat16(v - __bfloat162float(hi));
}
__device__ __forceinline__ uint32_t pack2(__nv_bfloat16 a, __nv_bfloat16 b) {
    __nv_bfloat162 t; t.x = a; t.y = b;
    return *reinterpret_cast<uint32_t*>(&t);
}
// swizzled byte offset within a [rows][64 bf16] tile (128B rows)
__device__ __forceinline__ int swz(int r, int cB) { return (r*128 + cB) ^ ((r & 7) << 4); }

__global__ void zero_s_kernel() { if (threadIdx.x < 24) g_s[threadIdx.x] = 0.0f; }

// split + transpose weights into [n][kk] tiles
__global__ void __launch_bounds__(256) wprep_kernel(const float* __restrict__ L, const float* __restrict__ R) {
    int b = blockIdx.x;
    int ch = b & 3, nt = (b >> 2) & 3, mat = (b >> 4) & 1, k = b >> 5;
    const float* W = (mat ? R : L) + (size_t)k*HID*HID;
    __nv_bfloat16* th = g_w + W_IDX(k, mat, 0, nt, ch);
    __nv_bfloat16* tl = g_w + W_IDX(k, mat, 1, nt, ch);
    for (int e = threadIdx.x; e < 4096; e += 256) {
        int n = e >> 6, kk = e & 63;
        float w = W[(size_t)(ch*64 + kk)*HID + nt*64 + n];
        __nv_bfloat16 hi, lo; split_bf(w, hi, lo);
        th[n*64 + kk] = hi; tl[n*64 + kk] = lo;
    }
}

// split x,h into g_act[0], g_act[1]
__global__ void __launch_bounds__(256) xconv_kernel(const float* __restrict__ x, const float* __restrict__ h) {
    size_t i = (size_t)blockIdx.x*256 + threadIdx.x;
    if (i >= (size_t)BATCH*HID/4) return;
    #pragma unroll
    for (int t = 0; t < 2; t++) {
        const float4 v = reinterpret_cast<const float4*>(t ? h : x)[i];
        __nv_bfloat16 h0,h1,h2,h3,l0,l1,l2,l3;
        split_bf(v.x,h0,l0); split_bf(v.y,h1,l1); split_bf(v.z,h2,l2); split_bf(v.w,h3,l3);
        uint2 uh; uh.x = pack2(h0,h1); uh.y = pack2(h2,h3);
        uint2 ul; ul.x = pack2(l0,l1); ul.y = pack2(l2,l3);
        reinterpret_cast<uint2*>(&g_act[t][0][0])[i] = uh;
        reinterpret_cast<uint2*>(&g_act[t][1][0])[i] = ul;
    }
}

// one 64-k chunk of HMMA accumulation
__device__ __forceinline__ void compute_chunk(float (&acc)[64], uint32_t XS, uint32_t WS,
                                              int lane, int wm, int wn) {
    const int kh  = (lane >> 4) * 16;           // byte offset of k-half
    const int rA  = wm*64 + (lane & 15);
    const int nB0 = wn*32 + (lane & 15);
    #pragma unroll
    for (int ks = 0; ks < 4; ks++) {
        const int cB = ks*32 + kh;
        uint32_t B0[4], B1[4];
        ldsm4(B0, WS + swz(nB0,      cB));
        ldsm4(B1, WS + swz(nB0 + 16, cB));
        #pragma unroll
        for (int fm = 0; fm < 4; fm++) {
            uint32_t A[4];
            ldsm4(A, XS + swz(rA + fm*16, cB));
            mma16816(&acc[(fm*4+0)*4], A, B0[0], B0[2]);
            mma16816(&acc[(fm*4+1)*4], A, B0[1], B0[3]);
            mma16816(&acc[(fm*4+2)*4], A, B1[0], B1[2]);
            mma16816(&acc[(fm*4+3)*4], A, B1[1], B1[3]);
        }
    }
}

// MODE: 0 LIN (A@L_e + B@R_e) -> cand
//       1 OMZ (A@R_e)         -> cand
//       2 MUL (A@L_e)*(B@R_e) -> cand
//       3 Z1R (A@L_e + B@R_e, sigmoid) -> gnode slots + act splits   (e in {0,1})
// smem (dyn 64KB): X bufs @0,@16384 ; W bufs @32768,@49152  (each 128 rows x 64 bf16, swizzled)
template<int MODE>
__global__ void __launch_bounds__(256, (MODE==2) ? 1 : 2)
mma_stage(const __nv_bfloat16* __restrict__ aHi, const __nv_bfloat16* __restrict__ aLo,
          const __nv_bfloat16* __restrict__ bHi, const __nv_bfloat16* __restrict__ bLo,
          const float* __restrict__ bvec, float* __restrict__ gnode)
{
    extern __shared__ char smem[];
    const uint32_t sb = smem_u32(smem);
    const int tid = threadIdx.x, lane = tid & 31, warp = tid >> 5;
    const int wm = warp >> 2, wn = warp & 3;
    const int mtile = blockIdx.x, nt = blockIdx.y, e = blockIdx.z;
    const int NIT = ((MODE == 1) ? 1 : 2) * 12;

    float accA[64];
    float accB[64];
    #pragma unroll
    for (int i = 0; i < 64; i++) accA[i] = 0.0f;
    if (MODE == 2) {
        #pragma unroll
        for (int i = 0; i < 64; i++) accB[i] = 0.0f;
    }

    // ---- async load of iteration it into buffer buf ----
    auto load_iter = [&](int it, int buf) {
        const int op = it / 12, rem = it % 12, p = rem >> 2, ch = rem & 3;
        const int xs = (p == 2), ws = (p == 1);
        const int mat = (MODE == 1) ? 1 : op;
        const __nv_bfloat16* xp = op ? (xs ? bLo : bHi) : (xs ? aLo : aHi);
        const uint32_t xbase = sb + buf*16384;
        #pragma unroll
        for (int q = 0; q < 4; q++) {
            int s = tid + q*256;
            int r = s >> 3, sg = s & 7;
            cpasync16(xbase + swz(r, sg*16),
                      xp + (size_t)(mtile*128 + r)*HID + ch*64 + sg*8);
        }
        const uint32_t wbase = sb + 32768 + buf*16384;
        #pragma unroll
        for (int q = 0; q < 4; q++) {
            int s = tid + q*256;
            int n = s >> 3, sg = s & 7;
            int ng = nt*128 + n;
            cpasync16(wbase + swz(n, sg*16),
                      g_w + W_IDX(e, mat, ws, (ng >> 6), ch) + (ng & 63)*64 + sg*8);
        }
    };

    load_iter(0, 0); CP_COMMIT();
    for (int it = 0; it < NIT; it++) {
        if (it + 1 < NIT) { load_iter(it + 1, (it + 1) & 1); CP_COMMIT(); CP_WAIT(1); }
        else              { CP_WAIT(0); }
        __syncthreads();
        const uint32_t XS = sb + (it & 1)*16384;
        const uint32_t WS = sb + 32768 + (it & 1)*16384;
        if (MODE == 2 && it >= 12) compute_chunk(accB, XS, WS, lane, wm, wn);
        else                       compute_chunk(accA, XS, WS, lane, wm, wn);
        __syncthreads();
    }

    // ---- epilogue ----
    const int r0 = mtile*128 + wm*64 + (lane >> 2);
    const int c0 = nt*128 + wn*32 + (lane & 3)*2;
    if (MODE == 3) {
        #pragma unroll
        for (int fm = 0; fm < 4; fm++)
        #pragma unroll
        for (int fn = 0; fn < 4; fn++)
        #pragma unroll
        for (int h2 = 0; h2 < 2; h2++) {
            const int row = r0 + fm*16 + h2*8;
            const int col = c0 + fn*8;
            #pragma unroll
            for (int j = 0; j < 2; j++) {
                float v = accA[(fm*4+fn)*4 + h2*2 + j] + bvec[e*HID + col + j];
                float z = 1.0f / (1.0f + expf(-v));
                gnode[(size_t)row*GN_STRIDE + e*HID + col + j] = z;
                if (e == 0) gnode[(size_t)row*GN_STRIDE + 2*HID + col + j] = z;
                __nv_bfloat16 hi, lo; split_bf(z, hi, lo);
                g_act[2 + e][0][(size_t)row*HID + col + j] = hi;
                g_act[2 + e][1][(size_t)row*HID + col + j] = lo;
            }
        }
    } else {
        #pragma unroll
        for (int fm = 0; fm < 4; fm++)
        #pragma unroll
        for (int fn = 0; fn < 4; fn++)
        #pragma unroll
        for (int h2 = 0; h2 < 2; h2++) {
            const int row = r0 + fm*16 + h2*8;
            const int col = c0 + fn*8;
            const int ix = (fm*4+fn)*4 + h2*2;
            float v0 = accA[ix], v1 = accA[ix + 1];
            if (MODE == 2) { v0 *= accB[ix]; v1 *= accB[ix + 1]; }
            float2 st; st.x = v0; st.y = v1;
            *reinterpret_cast<float2*>(&g_cand[((size_t)row*3 + e)*HID + col]) = st;
        }
    }
}

// per-row mixture: bias + k=3 candidate (identity weights) + softmax combine + outputs + next-stage splits
template<int MODE>
__global__ void __launch_bounds__(256)
mixture_kernel(const float* __restrict__ A, long sA,
               const float* __restrict__ Bv, long sB,
               const float* __restrict__ bvec, const float* __restrict__ Ws,
               float* __restrict__ outSlot, float* __restrict__ out2,
               __nv_bfloat16* __restrict__ actHi, __nv_bfloat16* __restrict__ actLo,
               float* __restrict__ s_acc)
{
    __shared__ float ss[4];
    const int tid = threadIdx.x, rl = tid >> 5, lane = tid & 31;
    const long row = (long)blockIdx.x*8 + rl;
    const int c0 = lane*8;
    if (tid < 4) ss[tid] = 0.0f;
    __syncthreads();

    float cf[4][8], w8[8];
    #pragma unroll
    for (int j = 0; j < 8; j++) w8[j] = Ws[c0 + j];

    #pragma unroll
    for (int k = 0; k < 3; k++) {
        const float* cp = g_cand + ((size_t)row*3 + k)*HID + c0;
        float4 v0 = reinterpret_cast<const float4*>(cp)[0];
        float4 v1 = reinterpret_cast<const float4*>(cp)[1];
        float vv[8] = {v0.x, v0.y, v0.z, v0.w, v1.x, v1.y, v1.z, v1.w};
        #pragma unroll
        for (int j = 0; j < 8; j++) {
            float t = vv[j] + bvec[k*HID + c0 + j];
            cf[k][j] = (MODE == 1) ? (1.0f - t) : t;
        }
    }
    #pragma unroll
    for (int j = 0; j < 8; j++) {
        float a  = A[row*sA + c0 + j];
        float b3 = bvec[3*HID + c0 + j];
        if (MODE == 0)      cf[3][j] = a + Bv[row*sB + c0 + j] + b3;
        else if (MODE == 1) cf[3][j] = 1.0f - (a + b3);
        else                cf[3][j] = a * Bv[row*sB + c0 + j] + b3;
    }
    float d[4];
    #pragma unroll
    for (int k = 0; k < 4; k++) {
        float t = 0.f;
        #pragma unroll
        for (int j = 0; j < 8; j++) t = fmaf(cf[k][j], w8[j], t);
        #pragma unroll
        for (int off = 16; off; off >>= 1) t += __shfl_xor_sync(0xffffffffu, t, off);
        d[k] = t;
    }
    if (lane == 0) {
        atomicAdd(&ss[0], d[0]); atomicAdd(&ss[1], d[1]);
        atomicAdd(&ss[2], d[2]); atomicAdd(&ss[3], d[3]);
    }
    float mx = fmaxf(fmaxf(d[0], d[1]), fmaxf(d[2], d[3]));
    float e0 = expf(d[0]-mx), e1 = expf(d[1]-mx), e2 = expf(d[2]-mx), e3 = expf(d[3]-mx);
    float inv = 1.0f / (e0 + e1 + e2 + e3);
    float w0 = e0*inv, w1 = e1*inv, w2 = e2*inv, w3 = e3*inv;

    float o[8];
    #pragma unroll
    for (int j = 0; j < 8; j++)
        o[j] = w0*cf[0][j] + w1*cf[1][j] + w2*cf[2][j] + w3*cf[3][j];

    float* os = outSlot + row*GN_STRIDE + c0;
    #pragma unroll
    for (int j = 0; j < 8; j++) os[j] = o[j];
    if (out2) {
        float4 u0 = make_float4(o[0], o[1], o[2], o[3]);
        float4 u1 = make_float4(o[4], o[5], o[6], o[7]);
        reinterpret_cast<float4*>(out2 + row*HID + c0)[0] = u0;
        reinterpret_cast<float4*>(out2 + row*HID + c0)[1] = u1;
    }
    if (actHi) {
        __nv_bfloat16 hi[8], lo[8];
        #pragma unroll
        for (int j = 0; j < 8; j++) split_bf(o[j], hi[j], lo[j]);
        uint4 uh, ul;
        uh.x = pack2(hi[0],hi[1]); uh.y = pack2(hi[2],hi[3]); uh.z = pack2(hi[4],hi[5]); uh.w = pack2(hi[6],hi[7]);
        ul.x = pack2(lo[0],lo[1]); ul.y = pack2(lo[2],lo[3]); ul.z = pack2(lo[4],lo[5]); ul.w = pack2(lo[6],lo[7]);
        *reinterpret_cast<uint4*>(actHi + row*HID + c0) = uh;
        *reinterpret_cast<uint4*>(actLo + row*HID + c0) = ul;
    }
    __syncthreads();
    if (tid < 4) atomicAdd(&s_acc[tid], ss[tid]);
}

__global__ void finalize_kernel(float* __restrict__ out) {
    if (threadIdx.x == 0 && blockIdx.x == 0) {
        float* gstr = out + OFF_GSTR;
        float* mg   = out + OFF_MARG;
        gstr[0] = 0.0f; gstr[1] = 1.0f; gstr[2] = 0.0f;
        for (int st = 0; st < 6; st++) {
            float s[4] = {g_s[st*4+0], g_s[st*4+1], g_s[st*4+2], g_s[st*4+3]};
            int idx = 0; float best = s[0];
            #pragma unroll
            for (int i = 1; i < 4; i++) if (s[i] > best) { best = s[i]; idx = i; }
            float second = -INFINITY;
            #pragma unroll
            for (int i = 0; i < 4; i++) if (i != idx) second = fmaxf(second, s[i]);
            gstr[3 + st] = (float)idx;
            mg[st] = best - second;
        }
    }
}

extern "C" void kernel_launch(void* const* d_in, const int* in_sizes, int n_in,
                              void* d_out, int out_size)
{
    const float* x  = (const float*)d_in[0];
    const float* h  = (const float*)d_in[1];
    const float* L  = (const float*)d_in[2];
    const float* R  = (const float*)d_in[3];
    const float* b  = (const float*)d_in[4];
    const float* Ws = (const float*)d_in[5];
    float* out = (float*)d_out;
    float* gnode = out + OFF_GNODE;

    const int SMEM = 65536;
    cudaFuncSetAttribute((const void*)mma_stage<0>, cudaFuncAttributeMaxDynamicSharedMemorySize, SMEM);
    cudaFuncSetAttribute((const void*)mma_stage<1>, cudaFuncAttributeMaxDynamicSharedMemorySize, SMEM);
    cudaFuncSetAttribute((const void*)mma_stage<2>, cudaFuncAttributeMaxDynamicSharedMemorySize, SMEM);
    cudaFuncSetAttribute((const void*)mma_stage<3>, cudaFuncAttributeMaxDynamicSharedMemorySize, SMEM);

    float* s_dev = nullptr;
    cudaGetSymbolAddress((void**)&s_dev, g_s);
    __nv_bfloat16* actB = nullptr;
    cudaGetSymbolAddress((void**)&actB, g_act);
    auto act = [&](int t, int sp) { return actB + ((size_t)t*2 + sp)*((size_t)BATCH*HID); };

    zero_s_kernel<<<1, 32>>>();
    wprep_kernel<<<96, 256>>>(L, R);
    xconv_kernel<<<(BATCH*HID/4 + 255)/256, 256>>>(x, h);

    const dim3 G3(128, 2, 3), G2(128, 2, 2);
    const int GM = BATCH/8;   // 2048

    // z1 (slots 0,2) + r (slot 1), sigmoid epilogue, splits -> act2 (z1), act3 (r)
    mma_stage<3><<<G2, 256, SMEM>>>(act(0,0), act(0,1), act(1,0), act(1,1), b, gnode);

    // s1: rh = mix(h@L + r@R + b) -> slot3, act4
    mma_stage<0><<<G3, 256, SMEM>>>(act(1,0), act(1,1), act(3,0), act(3,1), nullptr, nullptr);
    mixture_kernel<0><<<GM, 256>>>(h, (long)HID, gnode + 1*HID, (long)GN_STRIDE, b, Ws,
                                   gnode + 3*HID, nullptr, act(4,0), act(4,1), s_dev + 0);
    // s2: h_tilde = mix(x@L + rh@R + b) -> slot4, act5
    mma_stage<0><<<G3, 256, SMEM>>>(act(0,0), act(0,1), act(4,0), act(4,1), nullptr, nullptr);
    mixture_kernel<0><<<GM, 256>>>(x, (long)HID, gnode + 3*HID, (long)GN_STRIDE, b, Ws,
                                   gnode + 4*HID, nullptr, act(5,0), act(5,1), s_dev + 4);
    // s3: omz = mix(1 - (z1@R + b)) -> slot5, act6
    mma_stage<1><<<G3, 256, SMEM>>>(act(2,0), act(2,1), nullptr, nullptr, nullptr, nullptr);
    mixture_kernel<1><<<GM, 256>>>(gnode + 0*HID, (long)GN_STRIDE, nullptr, 0, b, Ws,
                                   gnode + 5*HID, nullptr, act(6,0), act(6,1), s_dev + 8);
    // s4: zh_tilde = mix((h_tilde@L)*(omz@R) + b) -> slot6, act7
    mma_stage<2><<<G3, 256, SMEM>>>(act(5,0), act(5,1), act(6,0), act(6,1), nullptr, nullptr);
    mixture_kernel<2><<<GM, 256>>>(gnode + 4*HID, (long)GN_STRIDE, gnode + 5*HID, (long)GN_STRIDE, b, Ws,
                                   gnode + 6*HID, nullptr, act(7,0), act(7,1), s_dev + 12);
    // s5: z2h = mix((h@L)*(z1@R) + b) -> slot7, act8
    mma_stage<2><<<G3, 256, SMEM>>>(act(1,0), act(1,1), act(2,0), act(2,1), nullptr, nullptr);
    mixture_kernel<2><<<GM, 256>>>(h, (long)HID, gnode + 0*HID, (long)GN_STRIDE, b, Ws,
                                   gnode + 7*HID, nullptr, act(8,0), act(8,1), s_dev + 16);
    // s6: h_next = mix(zh@L + z2h@R + b) -> slot8 + h_next output
    mma_stage<0><<<G3, 256, SMEM>>>(act(7,0), act(7,1), act(8,0), act(8,1), nullptr, nullptr);
    mixture_kernel<0><<<GM, 256>>>(gnode + 6*HID, (long)GN_STRIDE, gnode + 7*HID, (long)GN_STRIDE, b, Ws,
                                   gnode + 8*HID, out + OFF_HNEXT, nullptr, nullptr, s_dev + 20);

    finalize_kernel<<<1, 32>>>(out);
}